// round 8
// baseline (speedup 1.0000x reference)
#include <cuda_runtime.h>
#include <math_constants.h>
#include <cstdint>

#define D_   512
#define K_   32
#define N_   50000
#define B_   4096
#define H_   8
#define FF_  2048
#define L_   6
#define HD_  64
#define NKV  33
#define EPS_ 1e-5f

// ------------------------- scratch (static device memory) -------------------------
__device__ float g_scores[(size_t)B_ * N_];        // 819 MB
__device__ float g_topv[B_ * K_];
__device__ int   g_topi[B_ * K_];
__device__ float g_kv[(size_t)B_ * NKV * D_];      // 277 MB
__device__ float g_t[B_ * D_];
__device__ float g_q[B_ * D_];
__device__ float g_u[(size_t)B_ * H_ * D_];        // 67 MB
__device__ float g_c[(size_t)B_ * H_ * D_];        // 67 MB
__device__ float g_o[B_ * D_];
__device__ float g_buf1[(size_t)B_ * FF_];         // 33.5 MB
__device__ float g_buf2[B_ * D_];
__device__ float g_buf3[B_ * D_];
__device__ float g_coarse[B_ * D_];

__device__ __forceinline__ float wsum(float v) {
#pragma unroll
    for (int o = 16; o; o >>= 1) v += __shfl_xor_sync(0xffffffffu, v, o);
    return v;
}

// ------------------------- generic fp32 tiled GEMM -------------------------
// C[M,N] = A[M,K] @ op(B) + bias, op(B) = B[N,K]^T (TRANSB) or B[K,N] (NN).
// blockIdx.z batches independent problems (per-head GEMMs) via zs* strides.
template <bool TRANSB, bool RELU>
__global__ void __launch_bounds__(256) gemm_kernel(
    const float* __restrict__ Ag, const float* __restrict__ Bg,
    const float* __restrict__ biasg, float* __restrict__ Cg,
    int M, int N, int K, int lda, int ldb, int ldc,
    int zsA, int zsB, int zsC, int zsBias)
{
    const float* A = Ag + (size_t)blockIdx.z * zsA;
    const float* B = Bg + (size_t)blockIdx.z * zsB;
    float* C = Cg + (size_t)blockIdx.z * zsC;

    __shared__ float As[16][128];
    __shared__ float Bs[16][128];

    const int n0 = blockIdx.x * 128;
    const int m0 = blockIdx.y * 128;
    const int tid = threadIdx.x;
    const int tx = tid & 15;
    const int ty = tid >> 4;

    float acc[8][8];
#pragma unroll
    for (int i = 0; i < 8; i++)
#pragma unroll
        for (int j = 0; j < 8; j++) acc[i][j] = 0.f;

    for (int k0 = 0; k0 < K; k0 += 16) {
#pragma unroll
        for (int l = 0; l < 2; l++) {
            int fidx = (tid + l * 256) * 4;
            int ar = fidx >> 4;
            int ac = fidx & 15;
            float4 v = *reinterpret_cast<const float4*>(A + (size_t)(m0 + ar) * lda + k0 + ac);
            As[ac + 0][ar] = v.x; As[ac + 1][ar] = v.y;
            As[ac + 2][ar] = v.z; As[ac + 3][ar] = v.w;
        }
        if (TRANSB) {
#pragma unroll
            for (int l = 0; l < 2; l++) {
                int fidx = (tid + l * 256) * 4;
                int br = fidx >> 4;   // n within tile
                int bc = fidx & 15;   // k within tile
                float4 v = make_float4(0.f, 0.f, 0.f, 0.f);
                if (n0 + br < N)
                    v = *reinterpret_cast<const float4*>(B + (size_t)(n0 + br) * ldb + k0 + bc);
                Bs[bc + 0][br] = v.x; Bs[bc + 1][br] = v.y;
                Bs[bc + 2][br] = v.z; Bs[bc + 3][br] = v.w;
            }
        } else {
#pragma unroll
            for (int l = 0; l < 2; l++) {
                int fidx = (tid + l * 256) * 4;
                int bk = fidx >> 7;   // k within tile
                int bn = fidx & 127;  // n within tile
                float4 v = make_float4(0.f, 0.f, 0.f, 0.f);
                if (n0 + bn < N)
                    v = *reinterpret_cast<const float4*>(B + (size_t)(k0 + bk) * ldb + n0 + bn);
                *reinterpret_cast<float4*>(&Bs[bk][bn]) = v;
            }
        }
        __syncthreads();
#pragma unroll
        for (int kk = 0; kk < 16; kk++) {
            float a[8], bb[8];
#pragma unroll
            for (int i = 0; i < 8; i++) a[i] = As[kk][ty * 8 + i];
#pragma unroll
            for (int j = 0; j < 8; j++) bb[j] = Bs[kk][tx * 8 + j];
#pragma unroll
            for (int i = 0; i < 8; i++)
#pragma unroll
                for (int j = 0; j < 8; j++) acc[i][j] = fmaf(a[i], bb[j], acc[i][j]);
        }
        __syncthreads();
    }

    const float* bias = biasg ? biasg + (size_t)blockIdx.z * zsBias : nullptr;
#pragma unroll
    for (int i = 0; i < 8; i++) {
        int m = m0 + ty * 8 + i;
#pragma unroll
        for (int j = 0; j < 8; j++) {
            int n = n0 + tx * 8 + j;
            if (n < N) {
                float v = acc[i][j];
                if (bias) v += bias[n];
                if (RELU) v = fmaxf(v, 0.f);
                C[(size_t)m * ldc + n] = v;
            }
        }
    }
}

// ------------------------- top-32 per row (descending, jax tie-break) -------------------------
__global__ void __launch_bounds__(256) topk_kernel(const float* __restrict__ scores,
                                                   float* __restrict__ topv,
                                                   int* __restrict__ topi)
{
    extern __shared__ float sm[];
    float* sv = sm;                   // 8192 floats
    int* si = (int*)(sm + 8192);      // 8192 ints
    __shared__ float rv[8];
    __shared__ int ri[8];
    __shared__ int rp[8];

    const int b = blockIdx.x;
    const int tid = threadIdx.x;
    const int lane = tid & 31, warp = tid >> 5;
    const float* row = scores + (size_t)b * N_;

    // per-thread local top-32 (sorted descending; stable -> lower index first on ties)
    float lv[32]; int li[32];
#pragma unroll
    for (int i = 0; i < 32; i++) { lv[i] = -CUDART_INF_F; li[i] = 0x7fffffff; }
    for (int j = tid; j < N_; j += 256) {
        float v = row[j];
        if (v > lv[31]) {
            int p = 31;
            while (p > 0 && lv[p - 1] < v) { lv[p] = lv[p - 1]; li[p] = li[p - 1]; p--; }
            lv[p] = v; li[p] = j;
        }
    }
#pragma unroll
    for (int i = 0; i < 32; i++) { sv[tid * 32 + i] = lv[i]; si[tid * 32 + i] = li[i]; }
    __syncthreads();

    // 32 rounds of block argmax over 8192 candidates
    for (int r = 0; r < 32; r++) {
        float bv = -CUDART_INF_F; int bi = 0x7fffffff; int bp = -1;
        for (int p = tid; p < 8192; p += 256) {
            float v = sv[p];
            int idx = si[p];
            if (v > bv || (v == bv && idx < bi)) { bv = v; bi = idx; bp = p; }
        }
#pragma unroll
        for (int o = 16; o; o >>= 1) {
            float ov = __shfl_xor_sync(0xffffffffu, bv, o);
            int oi = __shfl_xor_sync(0xffffffffu, bi, o);
            int op = __shfl_xor_sync(0xffffffffu, bp, o);
            if (ov > bv || (ov == bv && oi < bi)) { bv = ov; bi = oi; bp = op; }
        }
        if (lane == 0) { rv[warp] = bv; ri[warp] = bi; rp[warp] = bp; }
        __syncthreads();
        if (tid == 0) {
            float fbv = rv[0]; int fbi = ri[0]; int fbp = rp[0];
#pragma unroll
            for (int w = 1; w < 8; w++)
                if (rv[w] > fbv || (rv[w] == fbv && ri[w] < fbi)) { fbv = rv[w]; fbi = ri[w]; fbp = rp[w]; }
            topv[b * 32 + r] = fbv;
            topi[b * 32 + r] = fbi;
            sv[fbp] = -CUDART_INF_F;
        }
        __syncthreads();
    }
}

// ------------------------- build KV: [x+te0 ; w*h_r + pos + te1] -------------------------
__global__ void __launch_bounds__(256) build_kv_kernel(
    const float* __restrict__ x, const float* __restrict__ cf,
    const float* __restrict__ te, const float* __restrict__ pos,
    const float* __restrict__ topv, const int* __restrict__ topi,
    float* __restrict__ kv)
{
    const int b = blockIdx.x;
    const int tid = threadIdx.x;
    __shared__ float w[32];
    if (tid < 32) {
        float m = topv[b * 32];               // sorted descending -> element 0 is the max
        float e = expf(topv[b * 32 + tid] - m);
        float s = e;
#pragma unroll
        for (int o = 16; o; o >>= 1) s += __shfl_xor_sync(0xffffffffu, s, o);
        w[tid] = e / s;
    }
    __syncthreads();
    float* kvb = kv + (size_t)b * NKV * D_;
    const float* xb = x + (size_t)b * D_;
    for (int d = tid; d < D_; d += 256) kvb[d] = xb[d] + te[d];
    for (int j = 0; j < 32; j++) {
        const float* h = cf + (size_t)topi[b * 32 + j] * D_;
        const float* pj = pos + j * D_;
        float wj = w[j];
        float* dst = kvb + (size_t)(j + 1) * D_;
        for (int d = tid; d < D_; d += 256) dst[d] = wj * h[d] + pj[d] + te[D_ + d];
    }
}

__global__ void init_t_kernel(float* __restrict__ t, const float* __restrict__ ce)
{
    t[(size_t)blockIdx.x * D_ + threadIdx.x] = ce[threadIdx.x];
}

// ------------------------- fused cross-attention core (per batch element) -------------------------
// logits_{h,j} = scale * ( u_h . kv_j + q_h . bk_h );  c_h = sum_j softmax_j * kv_j
__global__ void __launch_bounds__(256) attn_kernel(
    const float* __restrict__ q, const float* __restrict__ u,
    const float* __restrict__ kv, const float* __restrict__ bk,
    float* __restrict__ c)
{
    extern __shared__ float sm[];
    float* skv = sm;                  // NKV*D_
    float* su = sm + NKV * D_;        // H_*D_
    __shared__ float sq[D_];
    __shared__ float slog[H_ * NKV];
    __shared__ float sprob[H_ * NKV];
    __shared__ float sbeta[H_];

    const int b = blockIdx.x;
    const int tid = threadIdx.x;
    const int warp = tid >> 5, lane = tid & 31;

    const float* kvb = kv + (size_t)b * NKV * D_;
    const float* ub = u + (size_t)b * H_ * D_;
    const float* qb = q + (size_t)b * D_;
    for (int i = tid; i < NKV * D_; i += 256) skv[i] = kvb[i];
    for (int i = tid; i < H_ * D_; i += 256) su[i] = ub[i];
    for (int i = tid; i < D_; i += 256) sq[i] = qb[i];
    __syncthreads();

    { // beta_h = q_h . bk_h   (warp w -> head w)
        int h = warp;
        float s = sq[h * HD_ + lane] * bk[h * HD_ + lane]
                + sq[h * HD_ + 32 + lane] * bk[h * HD_ + 32 + lane];
        s = wsum(s);
        if (lane == 0) sbeta[h] = s;
    }
    __syncthreads();

    const float scale = 0.125f; // 1/sqrt(64)
    for (int p = warp; p < H_ * NKV; p += 8) {
        int h = p / NKV, j = p % NKV;
        const float* uh = su + h * D_;
        const float* kj = skv + j * D_;
        float s = 0.f;
#pragma unroll
        for (int d = lane; d < D_; d += 32) s += uh[d] * kj[d];
        s = wsum(s);
        if (lane == 0) slog[p] = (s + sbeta[h]) * scale;
    }
    __syncthreads();

    { // softmax over 33 keys, warp w -> head w
        int h = warp;
        float v0 = slog[h * NKV + lane];
        float v1 = (lane == 0) ? slog[h * NKV + 32] : -CUDART_INF_F;
        float m = fmaxf(v0, v1);
#pragma unroll
        for (int o = 16; o; o >>= 1) m = fmaxf(m, __shfl_xor_sync(0xffffffffu, m, o));
        float e0 = expf(v0 - m);
        float e1 = (lane == 0) ? expf(v1 - m) : 0.f;
        float s = wsum(e0 + e1);
        float inv = 1.f / s;
        sprob[h * NKV + lane] = e0 * inv;
        if (lane == 0) sprob[h * NKV + 32] = e1 * inv;
    }
    __syncthreads();

    float* cbp = c + (size_t)b * H_ * D_;
#pragma unroll
    for (int h = 0; h < H_; h++) {
        const float* pr = sprob + h * NKV;
        for (int d = tid; d < D_; d += 256) {
            float s = 0.f;
#pragma unroll
            for (int j = 0; j < NKV; j++) s += pr[j] * skv[j * D_ + d];
            cbp[h * D_ + d] = s;
        }
    }
}

// ------------------------- fused residual-add + LayerNorm (warp per row) -------------------------
__global__ void __launch_bounds__(256) add_ln_kernel(
    float* __restrict__ t, const float* __restrict__ r,
    const float* __restrict__ g, const float* __restrict__ bta)
{
    const int row = blockIdx.x * 8 + (threadIdx.x >> 5);
    const int lane = threadIdx.x & 31;
    float* tr = t + (size_t)row * D_;
    const float* rr = r + (size_t)row * D_;
    float v[16];
    float s = 0.f;
#pragma unroll
    for (int i = 0; i < 16; i++) { int d = lane + i * 32; v[i] = tr[d] + rr[d]; s += v[i]; }
    s = wsum(s);
    float mean = s * (1.f / D_);
    float s2 = 0.f;
#pragma unroll
    for (int i = 0; i < 16; i++) { float dd = v[i] - mean; s2 += dd * dd; }
    s2 = wsum(s2);
    float inv = rsqrtf(s2 * (1.f / D_) + EPS_);
#pragma unroll
    for (int i = 0; i < 16; i++) {
        int d = lane + i * 32;
        tr[d] = (v[i] - mean) * inv * g[d] + bta[d];
    }
}

// ------------------------- final: normalize(normalize(t) + normalize(coarse)) -------------------------
__global__ void __launch_bounds__(256) final_kernel(
    const float* __restrict__ t, const float* __restrict__ coarse,
    float* __restrict__ out)
{
    const int row = blockIdx.x * 8 + (threadIdx.x >> 5);
    const int lane = threadIdx.x & 31;
    const float* tr = t + (size_t)row * D_;
    const float* cr = coarse + (size_t)row * D_;
    float tv[16], cv[16];
    float st = 0.f, sc = 0.f;
#pragma unroll
    for (int i = 0; i < 16; i++) {
        int d = lane + i * 32;
        tv[i] = tr[d]; cv[i] = cr[d];
        st += tv[i] * tv[i]; sc += cv[i] * cv[i];
    }
    st = wsum(st); sc = wsum(sc);
    float rit = rsqrtf(st), ric = rsqrtf(sc);
    float av[16]; float sa = 0.f;
#pragma unroll
    for (int i = 0; i < 16; i++) { av[i] = tv[i] * rit + cv[i] * ric; sa += av[i] * av[i]; }
    sa = wsum(sa);
    float ra = rsqrtf(sa);
#pragma unroll
    for (int i = 0; i < 16; i++) {
        int d = lane + i * 32;
        out[(size_t)row * D_ + d] = av[i] * ra;
    }
}

// ------------------------- host orchestration -------------------------
static void gemmNT(const float* A, const float* B, const float* bias, float* C,
                   int M, int N, int K, int lda, int ldb, int ldc,
                   int Z = 1, int zsA = 0, int zsB = 0, int zsC = 0, int zsBias = 0,
                   bool relu = false)
{
    dim3 grid((N + 127) / 128, M / 128, Z);
    if (relu)
        gemm_kernel<true, true><<<grid, 256>>>(A, B, bias, C, M, N, K, lda, ldb, ldc, zsA, zsB, zsC, zsBias);
    else
        gemm_kernel<true, false><<<grid, 256>>>(A, B, bias, C, M, N, K, lda, ldb, ldc, zsA, zsB, zsC, zsBias);
}

static void gemmNN(const float* A, const float* B, const float* bias, float* C,
                   int M, int N, int K, int lda, int ldb, int ldc,
                   int Z = 1, int zsA = 0, int zsB = 0, int zsC = 0, int zsBias = 0)
{
    dim3 grid((N + 127) / 128, M / 128, Z);
    gemm_kernel<false, false><<<grid, 256>>>(A, B, bias, C, M, N, K, lda, ldb, ldc, zsA, zsB, zsC, zsBias);
}

extern "C" void kernel_launch(void* const* d_in, const int* in_sizes, int n_in,
                              void* d_out, int out_size)
{
    const float* x        = (const float*)d_in[0];
    const float* cf       = (const float*)d_in[1];
    const float* te       = (const float*)d_in[2];
    const float* pos      = (const float*)d_in[3];
    const float* ce       = (const float*)d_in[4];
    const float* sa_in_w  = (const float*)d_in[5];
    const float* sa_in_b  = (const float*)d_in[6];
    const float* sa_out_w = (const float*)d_in[7];
    const float* sa_out_b = (const float*)d_in[8];
    const float* ca_in_w  = (const float*)d_in[9];
    const float* ca_in_b  = (const float*)d_in[10];
    const float* ca_out_w = (const float*)d_in[11];
    const float* ca_out_b = (const float*)d_in[12];
    const float* lin1_w   = (const float*)d_in[13];
    const float* lin1_b   = (const float*)d_in[14];
    const float* lin2_w   = (const float*)d_in[15];
    const float* lin2_b   = (const float*)d_in[16];
    const float* ln1_g    = (const float*)d_in[17];
    const float* ln1_b    = (const float*)d_in[18];
    const float* ln2_g    = (const float*)d_in[19];
    const float* ln2_b    = (const float*)d_in[20];
    const float* ln3_g    = (const float*)d_in[21];
    const float* ln3_b    = (const float*)d_in[22];
    const float* region_w = (const float*)d_in[23];
    const float* region_b = (const float*)d_in[24];
    float* out = (float*)d_out;

    float *scores, *topv, *kvb, *tbuf, *qb, *ub, *cb, *ob, *buf1, *buf2, *buf3, *coarse;
    int* topi;
    cudaGetSymbolAddress((void**)&scores, g_scores);
    cudaGetSymbolAddress((void**)&topv,   g_topv);
    cudaGetSymbolAddress((void**)&topi,   g_topi);
    cudaGetSymbolAddress((void**)&kvb,    g_kv);
    cudaGetSymbolAddress((void**)&tbuf,   g_t);
    cudaGetSymbolAddress((void**)&qb,     g_q);
    cudaGetSymbolAddress((void**)&ub,     g_u);
    cudaGetSymbolAddress((void**)&cb,     g_c);
    cudaGetSymbolAddress((void**)&ob,     g_o);
    cudaGetSymbolAddress((void**)&buf1,   g_buf1);
    cudaGetSymbolAddress((void**)&buf2,   g_buf2);
    cudaGetSymbolAddress((void**)&buf3,   g_buf3);
    cudaGetSymbolAddress((void**)&coarse, g_coarse);

    cudaFuncSetAttribute(topk_kernel, cudaFuncAttributeMaxDynamicSharedMemorySize, 65536);
    const int attn_smem = (NKV * D_ + H_ * D_) * 4;
    cudaFuncSetAttribute(attn_kernel, cudaFuncAttributeMaxDynamicSharedMemorySize, attn_smem);

    // 1) concept scores + top-32 + KV assembly
    gemmNT(x, cf, nullptr, scores, B_, N_, D_, D_, D_, N_);
    topk_kernel<<<B_, 256, 65536>>>(scores, topv, topi);
    build_kv_kernel<<<B_, 256>>>(x, cf, te, pos, topv, topi, kvb);
    init_t_kernel<<<B_, D_>>>(tbuf, ce);

    const size_t DD = (size_t)D_ * D_;
    for (int i = 0; i < L_; i++) {
        const float* wv_sa = sa_in_w + i * 3 * DD + 2 * DD;
        const float* bv_sa = sa_in_b + i * 3 * D_ + 2 * D_;
        const float* wq    = ca_in_w + i * 3 * DD;
        const float* wk    = wq + DD;
        const float* wv    = wq + 2 * DD;
        const float* bq    = ca_in_b + i * 3 * D_;
        const float* bk    = bq + D_;
        const float* bv    = bq + 2 * D_;

        // --- self-attention over 1 token == two linear layers ---
        gemmNT(tbuf, wv_sa, bv_sa, buf2, B_, D_, D_, D_, D_, D_);
        gemmNT(buf2, sa_out_w + i * DD, sa_out_b + i * D_, buf3, B_, D_, D_, D_, D_, D_);
        add_ln_kernel<<<B_ / 8, 256>>>(tbuf, buf3, ln1_g + i * D_, ln1_b + i * D_);

        // --- cross-attention (factored: u = Wk_h^T q_h ; o_h = Wv_h c_h) ---
        gemmNT(tbuf, wq, bq, qb, B_, D_, D_, D_, D_, D_);
        gemmNN(qb, wk, nullptr, ub, B_, D_, HD_, D_, D_, H_ * D_,
               H_, HD_, HD_ * D_, D_, 0);
        attn_kernel<<<B_, 256, attn_smem>>>(qb, ub, kvb, bk, cb);
        gemmNT(cb, wv, bv, ob, B_, HD_, D_, H_ * D_, D_, D_,
               H_, D_, HD_ * D_, HD_, HD_);
        gemmNT(ob, ca_out_w + i * DD, ca_out_b + i * D_, buf3, B_, D_, D_, D_, D_, D_);
        add_ln_kernel<<<B_ / 8, 256>>>(tbuf, buf3, ln2_g + i * D_, ln2_b + i * D_);

        // --- feed-forward ---
        gemmNT(tbuf, lin1_w + (size_t)i * FF_ * D_, lin1_b + i * FF_, buf1,
               B_, FF_, D_, D_, D_, FF_, 1, 0, 0, 0, 0, true);
        gemmNT(buf1, lin2_w + (size_t)i * D_ * FF_, lin2_b + i * D_, buf3,
               B_, D_, FF_, FF_, FF_, D_);
        add_ln_kernel<<<B_ / 8, 256>>>(tbuf, buf3, ln3_g + i * D_, ln3_b + i * D_);
    }

    // 2) coarse branch + final combine
    gemmNT(x, region_w, region_b, coarse, B_, D_, D_, D_, D_, D_);
    final_kernel<<<B_ / 8, 256>>>(tbuf, coarse, out);
}

// round 9
// speedup vs baseline: 1.0049x; 1.0049x over previous
#include <cuda_runtime.h>
#include <math_constants.h>
#include <cstdint>

#define D_   512
#define K_   32
#define N_   50000
#define B_   4096
#define H_   8
#define FF_  2048
#define L_   6
#define HD_  64
#define NKV  33
#define EPS_ 1e-5f

// ------------------------- scratch (static device memory) -------------------------
__device__ float g_scores[(size_t)B_ * N_];        // 819 MB
__device__ float g_topv[B_ * K_];
__device__ int   g_topi[B_ * K_];
__device__ float g_kv[(size_t)B_ * NKV * D_];      // 277 MB
__device__ float g_t[B_ * D_];
__device__ float g_q[B_ * D_];
__device__ float g_u[(size_t)B_ * H_ * D_];        // 67 MB
__device__ float g_c[(size_t)B_ * H_ * D_];        // 67 MB
__device__ float g_o[B_ * D_];
__device__ float g_buf1[(size_t)B_ * FF_];         // 33.5 MB
__device__ float g_buf2[B_ * D_];
__device__ float g_buf3[B_ * D_];
__device__ float g_coarse[B_ * D_];

__device__ __forceinline__ float wsum(float v) {
#pragma unroll
    for (int o = 16; o; o >>= 1) v += __shfl_xor_sync(0xffffffffu, v, o);
    return v;
}

// ------------------------- generic fp32 tiled GEMM -------------------------
// C[M,N] = A[M,K] @ op(B) + bias, op(B) = B[N,K]^T (TRANSB) or B[K,N] (NN).
// blockIdx.z batches independent problems (per-head GEMMs) via zs* strides.
template <bool TRANSB, bool RELU>
__global__ void __launch_bounds__(256) gemm_kernel(
    const float* __restrict__ Ag, const float* __restrict__ Bg,
    const float* __restrict__ biasg, float* __restrict__ Cg,
    int M, int N, int K, int lda, int ldb, int ldc,
    int zsA, int zsB, int zsC, int zsBias)
{
    const float* A = Ag + (size_t)blockIdx.z * zsA;
    const float* B = Bg + (size_t)blockIdx.z * zsB;
    float* C = Cg + (size_t)blockIdx.z * zsC;

    __shared__ float As[16][128];
    __shared__ float Bs[16][128];

    const int n0 = blockIdx.x * 128;
    const int m0 = blockIdx.y * 128;
    const int tid = threadIdx.x;
    const int tx = tid & 15;
    const int ty = tid >> 4;

    float acc[8][8];
#pragma unroll
    for (int i = 0; i < 8; i++)
#pragma unroll
        for (int j = 0; j < 8; j++) acc[i][j] = 0.f;

    for (int k0 = 0; k0 < K; k0 += 16) {
#pragma unroll
        for (int l = 0; l < 2; l++) {
            int fidx = (tid + l * 256) * 4;
            int ar = fidx >> 4;
            int ac = fidx & 15;
            float4 v = *reinterpret_cast<const float4*>(A + (size_t)(m0 + ar) * lda + k0 + ac);
            As[ac + 0][ar] = v.x; As[ac + 1][ar] = v.y;
            As[ac + 2][ar] = v.z; As[ac + 3][ar] = v.w;
        }
        if (TRANSB) {
#pragma unroll
            for (int l = 0; l < 2; l++) {
                int fidx = (tid + l * 256) * 4;
                int br = fidx >> 4;   // n within tile
                int bc = fidx & 15;   // k within tile
                float4 v = make_float4(0.f, 0.f, 0.f, 0.f);
                if (n0 + br < N)
                    v = *reinterpret_cast<const float4*>(B + (size_t)(n0 + br) * ldb + k0 + bc);
                Bs[bc + 0][br] = v.x; Bs[bc + 1][br] = v.y;
                Bs[bc + 2][br] = v.z; Bs[bc + 3][br] = v.w;
            }
        } else {
#pragma unroll
            for (int l = 0; l < 2; l++) {
                int fidx = (tid + l * 256) * 4;
                int bk = fidx >> 7;   // k within tile
                int bn = fidx & 127;  // n within tile
                float4 v = make_float4(0.f, 0.f, 0.f, 0.f);
                if (n0 + bn < N)
                    v = *reinterpret_cast<const float4*>(B + (size_t)(k0 + bk) * ldb + n0 + bn);
                *reinterpret_cast<float4*>(&Bs[bk][bn]) = v;
            }
        }
        __syncthreads();
#pragma unroll
        for (int kk = 0; kk < 16; kk++) {
            float a[8], bb[8];
#pragma unroll
            for (int i = 0; i < 8; i++) a[i] = As[kk][ty * 8 + i];
#pragma unroll
            for (int j = 0; j < 8; j++) bb[j] = Bs[kk][tx * 8 + j];
#pragma unroll
            for (int i = 0; i < 8; i++)
#pragma unroll
                for (int j = 0; j < 8; j++) acc[i][j] = fmaf(a[i], bb[j], acc[i][j]);
        }
        __syncthreads();
    }

    const float* bias = biasg ? biasg + (size_t)blockIdx.z * zsBias : nullptr;
#pragma unroll
    for (int i = 0; i < 8; i++) {
        int m = m0 + ty * 8 + i;
#pragma unroll
        for (int j = 0; j < 8; j++) {
            int n = n0 + tx * 8 + j;
            if (n < N) {
                float v = acc[i][j];
                if (bias) v += bias[n];
                if (RELU) v = fmaxf(v, 0.f);
                C[(size_t)m * ldc + n] = v;
            }
        }
    }
}

// ------------------------- top-32 per row (descending, jax tie-break) -------------------------
__global__ void __launch_bounds__(256) topk_kernel(const float* __restrict__ scores,
                                                   float* __restrict__ topv,
                                                   int* __restrict__ topi)
{
    extern __shared__ float sm[];
    float* sv = sm;                   // 8192 floats
    int* si = (int*)(sm + 8192);      // 8192 ints
    __shared__ float rv[8];
    __shared__ int ri[8];
    __shared__ int rp[8];

    const int b = blockIdx.x;
    const int tid = threadIdx.x;
    const int lane = tid & 31, warp = tid >> 5;
    const float* row = scores + (size_t)b * N_;

    // per-thread local top-32 (sorted descending; stable -> lower index first on ties)
    float lv[32]; int li[32];
#pragma unroll
    for (int i = 0; i < 32; i++) { lv[i] = -CUDART_INF_F; li[i] = 0x7fffffff; }
    for (int j = tid; j < N_; j += 256) {
        float v = row[j];
        if (v > lv[31]) {
            int p = 31;
            while (p > 0 && lv[p - 1] < v) { lv[p] = lv[p - 1]; li[p] = li[p - 1]; p--; }
            lv[p] = v; li[p] = j;
        }
    }
#pragma unroll
    for (int i = 0; i < 32; i++) { sv[tid * 32 + i] = lv[i]; si[tid * 32 + i] = li[i]; }
    __syncthreads();

    // 32 rounds of block argmax over 8192 candidates
    for (int r = 0; r < 32; r++) {
        float bv = -CUDART_INF_F; int bi = 0x7fffffff; int bp = -1;
        for (int p = tid; p < 8192; p += 256) {
            float v = sv[p];
            int idx = si[p];
            if (v > bv || (v == bv && idx < bi)) { bv = v; bi = idx; bp = p; }
        }
#pragma unroll
        for (int o = 16; o; o >>= 1) {
            float ov = __shfl_xor_sync(0xffffffffu, bv, o);
            int oi = __shfl_xor_sync(0xffffffffu, bi, o);
            int op = __shfl_xor_sync(0xffffffffu, bp, o);
            if (ov > bv || (ov == bv && oi < bi)) { bv = ov; bi = oi; bp = op; }
        }
        if (lane == 0) { rv[warp] = bv; ri[warp] = bi; rp[warp] = bp; }
        __syncthreads();
        if (tid == 0) {
            float fbv = rv[0]; int fbi = ri[0]; int fbp = rp[0];
#pragma unroll
            for (int w = 1; w < 8; w++)
                if (rv[w] > fbv || (rv[w] == fbv && ri[w] < fbi)) { fbv = rv[w]; fbi = ri[w]; fbp = rp[w]; }
            topv[b * 32 + r] = fbv;
            topi[b * 32 + r] = fbi;
            sv[fbp] = -CUDART_INF_F;
        }
        __syncthreads();
    }
}

// ------------------------- build KV: [x+te0 ; w*h_r + pos + te1] -------------------------
__global__ void __launch_bounds__(256) build_kv_kernel(
    const float* __restrict__ x, const float* __restrict__ cf,
    const float* __restrict__ te, const float* __restrict__ pos,
    const float* __restrict__ topv, const int* __restrict__ topi,
    float* __restrict__ kv)
{
    const int b = blockIdx.x;
    const int tid = threadIdx.x;
    __shared__ float w[32];
    if (tid < 32) {
        float m = topv[b * 32];               // sorted descending -> element 0 is the max
        float e = expf(topv[b * 32 + tid] - m);
        float s = e;
#pragma unroll
        for (int o = 16; o; o >>= 1) s += __shfl_xor_sync(0xffffffffu, s, o);
        w[tid] = e / s;
    }
    __syncthreads();
    float* kvb = kv + (size_t)b * NKV * D_;
    const float* xb = x + (size_t)b * D_;
    for (int d = tid; d < D_; d += 256) kvb[d] = xb[d] + te[d];
    for (int j = 0; j < 32; j++) {
        const float* h = cf + (size_t)topi[b * 32 + j] * D_;
        const float* pj = pos + j * D_;
        float wj = w[j];
        float* dst = kvb + (size_t)(j + 1) * D_;
        for (int d = tid; d < D_; d += 256) dst[d] = wj * h[d] + pj[d] + te[D_ + d];
    }
}

__global__ void init_t_kernel(float* __restrict__ t, const float* __restrict__ ce)
{
    t[(size_t)blockIdx.x * D_ + threadIdx.x] = ce[threadIdx.x];
}

// ------------------------- fused cross-attention core (per batch element) -------------------------
// logits_{h,j} = scale * ( u_h . kv_j + q_h . bk_h );  c_h = sum_j softmax_j * kv_j
__global__ void __launch_bounds__(256) attn_kernel(
    const float* __restrict__ q, const float* __restrict__ u,
    const float* __restrict__ kv, const float* __restrict__ bk,
    float* __restrict__ c)
{
    extern __shared__ float sm[];
    float* skv = sm;                  // NKV*D_
    float* su = sm + NKV * D_;        // H_*D_
    __shared__ float sq[D_];
    __shared__ float slog[H_ * NKV];
    __shared__ float sprob[H_ * NKV];
    __shared__ float sbeta[H_];

    const int b = blockIdx.x;
    const int tid = threadIdx.x;
    const int warp = tid >> 5, lane = tid & 31;

    const float* kvb = kv + (size_t)b * NKV * D_;
    const float* ub = u + (size_t)b * H_ * D_;
    const float* qb = q + (size_t)b * D_;
    for (int i = tid; i < NKV * D_; i += 256) skv[i] = kvb[i];
    for (int i = tid; i < H_ * D_; i += 256) su[i] = ub[i];
    for (int i = tid; i < D_; i += 256) sq[i] = qb[i];
    __syncthreads();

    { // beta_h = q_h . bk_h   (warp w -> head w)
        int h = warp;
        float s = sq[h * HD_ + lane] * bk[h * HD_ + lane]
                + sq[h * HD_ + 32 + lane] * bk[h * HD_ + 32 + lane];
        s = wsum(s);
        if (lane == 0) sbeta[h] = s;
    }
    __syncthreads();

    const float scale = 0.125f; // 1/sqrt(64)
    for (int p = warp; p < H_ * NKV; p += 8) {
        int h = p / NKV, j = p % NKV;
        const float* uh = su + h * D_;
        const float* kj = skv + j * D_;
        float s = 0.f;
#pragma unroll
        for (int d = lane; d < D_; d += 32) s += uh[d] * kj[d];
        s = wsum(s);
        if (lane == 0) slog[p] = (s + sbeta[h]) * scale;
    }
    __syncthreads();

    { // softmax over 33 keys, warp w -> head w
        int h = warp;
        float v0 = slog[h * NKV + lane];
        float v1 = (lane == 0) ? slog[h * NKV + 32] : -CUDART_INF_F;
        float m = fmaxf(v0, v1);
#pragma unroll
        for (int o = 16; o; o >>= 1) m = fmaxf(m, __shfl_xor_sync(0xffffffffu, m, o));
        float e0 = expf(v0 - m);
        float e1 = (lane == 0) ? expf(v1 - m) : 0.f;
        float s = wsum(e0 + e1);
        float inv = 1.f / s;
        sprob[h * NKV + lane] = e0 * inv;
        if (lane == 0) sprob[h * NKV + 32] = e1 * inv;
    }
    __syncthreads();

    float* cbp = c + (size_t)b * H_ * D_;
#pragma unroll
    for (int h = 0; h < H_; h++) {
        const float* pr = sprob + h * NKV;
        for (int d = tid; d < D_; d += 256) {
            float s = 0.f;
#pragma unroll
            for (int j = 0; j < NKV; j++) s += pr[j] * skv[j * D_ + d];
            cbp[h * D_ + d] = s;
        }
    }
}

// ------------------------- fused residual-add + LayerNorm (warp per row) -------------------------
__global__ void __launch_bounds__(256) add_ln_kernel(
    float* __restrict__ t, const float* __restrict__ r,
    const float* __restrict__ g, const float* __restrict__ bta)
{
    const int row = blockIdx.x * 8 + (threadIdx.x >> 5);
    const int lane = threadIdx.x & 31;
    float* tr = t + (size_t)row * D_;
    const float* rr = r + (size_t)row * D_;
    float v[16];
    float s = 0.f;
#pragma unroll
    for (int i = 0; i < 16; i++) { int d = lane + i * 32; v[i] = tr[d] + rr[d]; s += v[i]; }
    s = wsum(s);
    float mean = s * (1.f / D_);
    float s2 = 0.f;
#pragma unroll
    for (int i = 0; i < 16; i++) { float dd = v[i] - mean; s2 += dd * dd; }
    s2 = wsum(s2);
    float inv = rsqrtf(s2 * (1.f / D_) + EPS_);
#pragma unroll
    for (int i = 0; i < 16; i++) {
        int d = lane + i * 32;
        tr[d] = (v[i] - mean) * inv * g[d] + bta[d];
    }
}

// ------------------------- final: normalize(normalize(t) + normalize(coarse)) -------------------------
__global__ void __launch_bounds__(256) final_kernel(
    const float* __restrict__ t, const float* __restrict__ coarse,
    float* __restrict__ out)
{
    const int row = blockIdx.x * 8 + (threadIdx.x >> 5);
    const int lane = threadIdx.x & 31;
    const float* tr = t + (size_t)row * D_;
    const float* cr = coarse + (size_t)row * D_;
    float tv[16], cv[16];
    float st = 0.f, sc = 0.f;
#pragma unroll
    for (int i = 0; i < 16; i++) {
        int d = lane + i * 32;
        tv[i] = tr[d]; cv[i] = cr[d];
        st += tv[i] * tv[i]; sc += cv[i] * cv[i];
    }
    st = wsum(st); sc = wsum(sc);
    float rit = rsqrtf(st), ric = rsqrtf(sc);
    float av[16]; float sa = 0.f;
#pragma unroll
    for (int i = 0; i < 16; i++) { av[i] = tv[i] * rit + cv[i] * ric; sa += av[i] * av[i]; }
    sa = wsum(sa);
    float ra = rsqrtf(sa);
#pragma unroll
    for (int i = 0; i < 16; i++) {
        int d = lane + i * 32;
        out[(size_t)row * D_ + d] = av[i] * ra;
    }
}

// ------------------------- host orchestration -------------------------
static void gemmNT(const float* A, const float* B, const float* bias, float* C,
                   int M, int N, int K, int lda, int ldb, int ldc,
                   int Z = 1, int zsA = 0, int zsB = 0, int zsC = 0, int zsBias = 0,
                   bool relu = false)
{
    dim3 grid((N + 127) / 128, M / 128, Z);
    if (relu)
        gemm_kernel<true, true><<<grid, 256>>>(A, B, bias, C, M, N, K, lda, ldb, ldc, zsA, zsB, zsC, zsBias);
    else
        gemm_kernel<true, false><<<grid, 256>>>(A, B, bias, C, M, N, K, lda, ldb, ldc, zsA, zsB, zsC, zsBias);
}

static void gemmNN(const float* A, const float* B, const float* bias, float* C,
                   int M, int N, int K, int lda, int ldb, int ldc,
                   int Z = 1, int zsA = 0, int zsB = 0, int zsC = 0, int zsBias = 0)
{
    dim3 grid((N + 127) / 128, M / 128, Z);
    gemm_kernel<false, false><<<grid, 256>>>(A, B, bias, C, M, N, K, lda, ldb, ldc, zsA, zsB, zsC, zsBias);
}

extern "C" void kernel_launch(void* const* d_in, const int* in_sizes, int n_in,
                              void* d_out, int out_size)
{
    const float* x        = (const float*)d_in[0];
    const float* cf       = (const float*)d_in[1];
    const float* te       = (const float*)d_in[2];
    const float* pos      = (const float*)d_in[3];
    const float* ce       = (const float*)d_in[4];
    const float* sa_in_w  = (const float*)d_in[5];
    const float* sa_in_b  = (const float*)d_in[6];
    const float* sa_out_w = (const float*)d_in[7];
    const float* sa_out_b = (const float*)d_in[8];
    const float* ca_in_w  = (const float*)d_in[9];
    const float* ca_in_b  = (const float*)d_in[10];
    const float* ca_out_w = (const float*)d_in[11];
    const float* ca_out_b = (const float*)d_in[12];
    const float* lin1_w   = (const float*)d_in[13];
    const float* lin1_b   = (const float*)d_in[14];
    const float* lin2_w   = (const float*)d_in[15];
    const float* lin2_b   = (const float*)d_in[16];
    const float* ln1_g    = (const float*)d_in[17];
    const float* ln1_b    = (const float*)d_in[18];
    const float* ln2_g    = (const float*)d_in[19];
    const float* ln2_b    = (const float*)d_in[20];
    const float* ln3_g    = (const float*)d_in[21];
    const float* ln3_b    = (const float*)d_in[22];
    const float* region_w = (const float*)d_in[23];
    const float* region_b = (const float*)d_in[24];
    float* out = (float*)d_out;

    float *scores, *topv, *kvb, *tbuf, *qb, *ub, *cb, *ob, *buf1, *buf2, *buf3, *coarse;
    int* topi;
    cudaGetSymbolAddress((void**)&scores, g_scores);
    cudaGetSymbolAddress((void**)&topv,   g_topv);
    cudaGetSymbolAddress((void**)&topi,   g_topi);
    cudaGetSymbolAddress((void**)&kvb,    g_kv);
    cudaGetSymbolAddress((void**)&tbuf,   g_t);
    cudaGetSymbolAddress((void**)&qb,     g_q);
    cudaGetSymbolAddress((void**)&ub,     g_u);
    cudaGetSymbolAddress((void**)&cb,     g_c);
    cudaGetSymbolAddress((void**)&ob,     g_o);
    cudaGetSymbolAddress((void**)&buf1,   g_buf1);
    cudaGetSymbolAddress((void**)&buf2,   g_buf2);
    cudaGetSymbolAddress((void**)&buf3,   g_buf3);
    cudaGetSymbolAddress((void**)&coarse, g_coarse);

    cudaFuncSetAttribute(topk_kernel, cudaFuncAttributeMaxDynamicSharedMemorySize, 65536);
    const int attn_smem = (NKV * D_ + H_ * D_) * 4;
    cudaFuncSetAttribute(attn_kernel, cudaFuncAttributeMaxDynamicSharedMemorySize, attn_smem);

    // 1) concept scores + top-32 + KV assembly
    gemmNT(x, cf, nullptr, scores, B_, N_, D_, D_, D_, N_);
    topk_kernel<<<B_, 256, 65536>>>(scores, topv, topi);
    build_kv_kernel<<<B_, 256>>>(x, cf, te, pos, topv, topi, kvb);
    init_t_kernel<<<B_, D_>>>(tbuf, ce);

    const size_t DD = (size_t)D_ * D_;
    for (int i = 0; i < L_; i++) {
        const float* wv_sa = sa_in_w + i * 3 * DD + 2 * DD;
        const float* bv_sa = sa_in_b + i * 3 * D_ + 2 * D_;
        const float* wq    = ca_in_w + i * 3 * DD;
        const float* wk    = wq + DD;
        const float* wv    = wq + 2 * DD;
        const float* bq    = ca_in_b + i * 3 * D_;
        const float* bk    = bq + D_;
        const float* bv    = bq + 2 * D_;

        // --- self-attention over 1 token == two linear layers ---
        gemmNT(tbuf, wv_sa, bv_sa, buf2, B_, D_, D_, D_, D_, D_);
        gemmNT(buf2, sa_out_w + i * DD, sa_out_b + i * D_, buf3, B_, D_, D_, D_, D_, D_);
        add_ln_kernel<<<B_ / 8, 256>>>(tbuf, buf3, ln1_g + i * D_, ln1_b + i * D_);

        // --- cross-attention (factored: u = Wk_h^T q_h ; o_h = Wv_h c_h) ---
        gemmNT(tbuf, wq, bq, qb, B_, D_, D_, D_, D_, D_);
        gemmNN(qb, wk, nullptr, ub, B_, D_, HD_, D_, D_, H_ * D_,
               H_, HD_, HD_ * D_, D_, 0);
        attn_kernel<<<B_, 256, attn_smem>>>(qb, ub, kvb, bk, cb);
        gemmNT(cb, wv, bv, ob, B_, HD_, D_, H_ * D_, D_, D_,
               H_, D_, HD_ * D_, HD_, HD_);
        gemmNT(ob, ca_out_w + i * DD, ca_out_b + i * D_, buf3, B_, D_, D_, D_, D_, D_);
        add_ln_kernel<<<B_ / 8, 256>>>(tbuf, buf3, ln2_g + i * D_, ln2_b + i * D_);

        // --- feed-forward ---
        gemmNT(tbuf, lin1_w + (size_t)i * FF_ * D_, lin1_b + i * FF_, buf1,
               B_, FF_, D_, D_, D_, FF_, 1, 0, 0, 0, 0, true);
        gemmNT(buf1, lin2_w + (size_t)i * D_ * FF_, lin2_b + i * D_, buf3,
               B_, D_, FF_, FF_, FF_, D_);
        add_ln_kernel<<<B_ / 8, 256>>>(tbuf, buf3, ln3_g + i * D_, ln3_b + i * D_);
    }

    // 2) coarse branch + final combine
    gemmNT(x, region_w, region_b, coarse, B_, D_, D_, D_, D_, D_);
    final_kernel<<<B_ / 8, 256>>>(tbuf, coarse, out);
}

// round 10
// speedup vs baseline: 1.0052x; 1.0003x over previous
#include <cuda_runtime.h>
#include <math_constants.h>
#include <cstdint>

#define D_   512
#define K_   32
#define N_   50000
#define B_   4096
#define H_   8
#define FF_  2048
#define L_   6
#define HD_  64
#define NKV  33
#define EPS_ 1e-5f

// ------------------------- scratch (static device memory) -------------------------
__device__ float g_scores[(size_t)B_ * N_];        // 819 MB
__device__ float g_topv[B_ * K_];
__device__ int   g_topi[B_ * K_];
__device__ float g_kv[(size_t)B_ * NKV * D_];      // 277 MB
__device__ float g_t[B_ * D_];
__device__ float g_q[B_ * D_];
__device__ float g_u[(size_t)B_ * H_ * D_];        // 67 MB
__device__ float g_c[(size_t)B_ * H_ * D_];        // 67 MB
__device__ float g_o[B_ * D_];
__device__ float g_buf1[(size_t)B_ * FF_];         // 33.5 MB
__device__ float g_buf2[B_ * D_];
__device__ float g_buf3[B_ * D_];
__device__ float g_coarse[B_ * D_];

__device__ __forceinline__ float wsum(float v) {
#pragma unroll
    for (int o = 16; o; o >>= 1) v += __shfl_xor_sync(0xffffffffu, v, o);
    return v;
}

// ------------------------- generic fp32 tiled GEMM -------------------------
// C[M,N] = A[M,K] @ op(B) + bias, op(B) = B[N,K]^T (TRANSB) or B[K,N] (NN).
// blockIdx.z batches independent problems (per-head GEMMs) via zs* strides.
template <bool TRANSB, bool RELU>
__global__ void __launch_bounds__(256) gemm_kernel(
    const float* __restrict__ Ag, const float* __restrict__ Bg,
    const float* __restrict__ biasg, float* __restrict__ Cg,
    int M, int N, int K, int lda, int ldb, int ldc,
    int zsA, int zsB, int zsC, int zsBias)
{
    const float* A = Ag + (size_t)blockIdx.z * zsA;
    const float* B = Bg + (size_t)blockIdx.z * zsB;
    float* C = Cg + (size_t)blockIdx.z * zsC;

    __shared__ float As[16][128];
    __shared__ float Bs[16][128];

    const int n0 = blockIdx.x * 128;
    const int m0 = blockIdx.y * 128;
    const int tid = threadIdx.x;
    const int tx = tid & 15;
    const int ty = tid >> 4;

    float acc[8][8];
#pragma unroll
    for (int i = 0; i < 8; i++)
#pragma unroll
        for (int j = 0; j < 8; j++) acc[i][j] = 0.f;

    for (int k0 = 0; k0 < K; k0 += 16) {
#pragma unroll
        for (int l = 0; l < 2; l++) {
            int fidx = (tid + l * 256) * 4;
            int ar = fidx >> 4;
            int ac = fidx & 15;
            float4 v = *reinterpret_cast<const float4*>(A + (size_t)(m0 + ar) * lda + k0 + ac);
            As[ac + 0][ar] = v.x; As[ac + 1][ar] = v.y;
            As[ac + 2][ar] = v.z; As[ac + 3][ar] = v.w;
        }
        if (TRANSB) {
#pragma unroll
            for (int l = 0; l < 2; l++) {
                int fidx = (tid + l * 256) * 4;
                int br = fidx >> 4;   // n within tile
                int bc = fidx & 15;   // k within tile
                float4 v = make_float4(0.f, 0.f, 0.f, 0.f);
                if (n0 + br < N)
                    v = *reinterpret_cast<const float4*>(B + (size_t)(n0 + br) * ldb + k0 + bc);
                Bs[bc + 0][br] = v.x; Bs[bc + 1][br] = v.y;
                Bs[bc + 2][br] = v.z; Bs[bc + 3][br] = v.w;
            }
        } else {
#pragma unroll
            for (int l = 0; l < 2; l++) {
                int fidx = (tid + l * 256) * 4;
                int bk = fidx >> 7;   // k within tile
                int bn = fidx & 127;  // n within tile
                float4 v = make_float4(0.f, 0.f, 0.f, 0.f);
                if (n0 + bn < N)
                    v = *reinterpret_cast<const float4*>(B + (size_t)(k0 + bk) * ldb + n0 + bn);
                *reinterpret_cast<float4*>(&Bs[bk][bn]) = v;
            }
        }
        __syncthreads();
#pragma unroll
        for (int kk = 0; kk < 16; kk++) {
            float a[8], bb[8];
#pragma unroll
            for (int i = 0; i < 8; i++) a[i] = As[kk][ty * 8 + i];
#pragma unroll
            for (int j = 0; j < 8; j++) bb[j] = Bs[kk][tx * 8 + j];
#pragma unroll
            for (int i = 0; i < 8; i++)
#pragma unroll
                for (int j = 0; j < 8; j++) acc[i][j] = fmaf(a[i], bb[j], acc[i][j]);
        }
        __syncthreads();
    }

    const float* bias = biasg ? biasg + (size_t)blockIdx.z * zsBias : nullptr;
#pragma unroll
    for (int i = 0; i < 8; i++) {
        int m = m0 + ty * 8 + i;
#pragma unroll
        for (int j = 0; j < 8; j++) {
            int n = n0 + tx * 8 + j;
            if (n < N) {
                float v = acc[i][j];
                if (bias) v += bias[n];
                if (RELU) v = fmaxf(v, 0.f);
                C[(size_t)m * ldc + n] = v;
            }
        }
    }
}

// ------------------------- top-32 per row (descending, jax tie-break) -------------------------
__global__ void __launch_bounds__(256) topk_kernel(const float* __restrict__ scores,
                                                   float* __restrict__ topv,
                                                   int* __restrict__ topi)
{
    extern __shared__ float sm[];
    float* sv = sm;                   // 8192 floats
    int* si = (int*)(sm + 8192);      // 8192 ints
    __shared__ float rv[8];
    __shared__ int ri[8];
    __shared__ int rp[8];

    const int b = blockIdx.x;
    const int tid = threadIdx.x;
    const int lane = tid & 31, warp = tid >> 5;
    const float* row = scores + (size_t)b * N_;

    // per-thread local top-32 (sorted descending; stable -> lower index first on ties)
    float lv[32]; int li[32];
#pragma unroll
    for (int i = 0; i < 32; i++) { lv[i] = -CUDART_INF_F; li[i] = 0x7fffffff; }
    for (int j = tid; j < N_; j += 256) {
        float v = row[j];
        if (v > lv[31]) {
            int p = 31;
            while (p > 0 && lv[p - 1] < v) { lv[p] = lv[p - 1]; li[p] = li[p - 1]; p--; }
            lv[p] = v; li[p] = j;
        }
    }
#pragma unroll
    for (int i = 0; i < 32; i++) { sv[tid * 32 + i] = lv[i]; si[tid * 32 + i] = li[i]; }
    __syncthreads();

    // 32 rounds of block argmax over 8192 candidates
    for (int r = 0; r < 32; r++) {
        float bv = -CUDART_INF_F; int bi = 0x7fffffff; int bp = -1;
        for (int p = tid; p < 8192; p += 256) {
            float v = sv[p];
            int idx = si[p];
            if (v > bv || (v == bv && idx < bi)) { bv = v; bi = idx; bp = p; }
        }
#pragma unroll
        for (int o = 16; o; o >>= 1) {
            float ov = __shfl_xor_sync(0xffffffffu, bv, o);
            int oi = __shfl_xor_sync(0xffffffffu, bi, o);
            int op = __shfl_xor_sync(0xffffffffu, bp, o);
            if (ov > bv || (ov == bv && oi < bi)) { bv = ov; bi = oi; bp = op; }
        }
        if (lane == 0) { rv[warp] = bv; ri[warp] = bi; rp[warp] = bp; }
        __syncthreads();
        if (tid == 0) {
            float fbv = rv[0]; int fbi = ri[0]; int fbp = rp[0];
#pragma unroll
            for (int w = 1; w < 8; w++)
                if (rv[w] > fbv || (rv[w] == fbv && ri[w] < fbi)) { fbv = rv[w]; fbi = ri[w]; fbp = rp[w]; }
            topv[b * 32 + r] = fbv;
            topi[b * 32 + r] = fbi;
            sv[fbp] = -CUDART_INF_F;
        }
        __syncthreads();
    }
}

// ------------------------- build KV: [x+te0 ; w*h_r + pos + te1] -------------------------
__global__ void __launch_bounds__(256) build_kv_kernel(
    const float* __restrict__ x, const float* __restrict__ cf,
    const float* __restrict__ te, const float* __restrict__ pos,
    const float* __restrict__ topv, const int* __restrict__ topi,
    float* __restrict__ kv)
{
    const int b = blockIdx.x;
    const int tid = threadIdx.x;
    __shared__ float w[32];
    if (tid < 32) {
        float m = topv[b * 32];               // sorted descending -> element 0 is the max
        float e = expf(topv[b * 32 + tid] - m);
        float s = e;
#pragma unroll
        for (int o = 16; o; o >>= 1) s += __shfl_xor_sync(0xffffffffu, s, o);
        w[tid] = e / s;
    }
    __syncthreads();
    float* kvb = kv + (size_t)b * NKV * D_;
    const float* xb = x + (size_t)b * D_;
    for (int d = tid; d < D_; d += 256) kvb[d] = xb[d] + te[d];
    for (int j = 0; j < 32; j++) {
        const float* h = cf + (size_t)topi[b * 32 + j] * D_;
        const float* pj = pos + j * D_;
        float wj = w[j];
        float* dst = kvb + (size_t)(j + 1) * D_;
        for (int d = tid; d < D_; d += 256) dst[d] = wj * h[d] + pj[d] + te[D_ + d];
    }
}

__global__ void init_t_kernel(float* __restrict__ t, const float* __restrict__ ce)
{
    t[(size_t)blockIdx.x * D_ + threadIdx.x] = ce[threadIdx.x];
}

// ------------------------- fused cross-attention core (per batch element) -------------------------
// logits_{h,j} = scale * ( u_h . kv_j + q_h . bk_h );  c_h = sum_j softmax_j * kv_j
__global__ void __launch_bounds__(256) attn_kernel(
    const float* __restrict__ q, const float* __restrict__ u,
    const float* __restrict__ kv, const float* __restrict__ bk,
    float* __restrict__ c)
{
    extern __shared__ float sm[];
    float* skv = sm;                  // NKV*D_
    float* su = sm + NKV * D_;        // H_*D_
    __shared__ float sq[D_];
    __shared__ float slog[H_ * NKV];
    __shared__ float sprob[H_ * NKV];
    __shared__ float sbeta[H_];

    const int b = blockIdx.x;
    const int tid = threadIdx.x;
    const int warp = tid >> 5, lane = tid & 31;

    const float* kvb = kv + (size_t)b * NKV * D_;
    const float* ub = u + (size_t)b * H_ * D_;
    const float* qb = q + (size_t)b * D_;
    for (int i = tid; i < NKV * D_; i += 256) skv[i] = kvb[i];
    for (int i = tid; i < H_ * D_; i += 256) su[i] = ub[i];
    for (int i = tid; i < D_; i += 256) sq[i] = qb[i];
    __syncthreads();

    { // beta_h = q_h . bk_h   (warp w -> head w)
        int h = warp;
        float s = sq[h * HD_ + lane] * bk[h * HD_ + lane]
                + sq[h * HD_ + 32 + lane] * bk[h * HD_ + 32 + lane];
        s = wsum(s);
        if (lane == 0) sbeta[h] = s;
    }
    __syncthreads();

    const float scale = 0.125f; // 1/sqrt(64)
    for (int p = warp; p < H_ * NKV; p += 8) {
        int h = p / NKV, j = p % NKV;
        const float* uh = su + h * D_;
        const float* kj = skv + j * D_;
        float s = 0.f;
#pragma unroll
        for (int d = lane; d < D_; d += 32) s += uh[d] * kj[d];
        s = wsum(s);
        if (lane == 0) slog[p] = (s + sbeta[h]) * scale;
    }
    __syncthreads();

    { // softmax over 33 keys, warp w -> head w
        int h = warp;
        float v0 = slog[h * NKV + lane];
        float v1 = (lane == 0) ? slog[h * NKV + 32] : -CUDART_INF_F;
        float m = fmaxf(v0, v1);
#pragma unroll
        for (int o = 16; o; o >>= 1) m = fmaxf(m, __shfl_xor_sync(0xffffffffu, m, o));
        float e0 = expf(v0 - m);
        float e1 = (lane == 0) ? expf(v1 - m) : 0.f;
        float s = wsum(e0 + e1);
        float inv = 1.f / s;
        sprob[h * NKV + lane] = e0 * inv;
        if (lane == 0) sprob[h * NKV + 32] = e1 * inv;
    }
    __syncthreads();

    float* cbp = c + (size_t)b * H_ * D_;
#pragma unroll
    for (int h = 0; h < H_; h++) {
        const float* pr = sprob + h * NKV;
        for (int d = tid; d < D_; d += 256) {
            float s = 0.f;
#pragma unroll
            for (int j = 0; j < NKV; j++) s += pr[j] * skv[j * D_ + d];
            cbp[h * D_ + d] = s;
        }
    }
}

// ------------------------- fused residual-add + LayerNorm (warp per row) -------------------------
__global__ void __launch_bounds__(256) add_ln_kernel(
    float* __restrict__ t, const float* __restrict__ r,
    const float* __restrict__ g, const float* __restrict__ bta)
{
    const int row = blockIdx.x * 8 + (threadIdx.x >> 5);
    const int lane = threadIdx.x & 31;
    float* tr = t + (size_t)row * D_;
    const float* rr = r + (size_t)row * D_;
    float v[16];
    float s = 0.f;
#pragma unroll
    for (int i = 0; i < 16; i++) { int d = lane + i * 32; v[i] = tr[d] + rr[d]; s += v[i]; }
    s = wsum(s);
    float mean = s * (1.f / D_);
    float s2 = 0.f;
#pragma unroll
    for (int i = 0; i < 16; i++) { float dd = v[i] - mean; s2 += dd * dd; }
    s2 = wsum(s2);
    float inv = rsqrtf(s2 * (1.f / D_) + EPS_);
#pragma unroll
    for (int i = 0; i < 16; i++) {
        int d = lane + i * 32;
        tr[d] = (v[i] - mean) * inv * g[d] + bta[d];
    }
}

// ------------------------- final: normalize(normalize(t) + normalize(coarse)) -------------------------
__global__ void __launch_bounds__(256) final_kernel(
    const float* __restrict__ t, const float* __restrict__ coarse,
    float* __restrict__ out)
{
    const int row = blockIdx.x * 8 + (threadIdx.x >> 5);
    const int lane = threadIdx.x & 31;
    const float* tr = t + (size_t)row * D_;
    const float* cr = coarse + (size_t)row * D_;
    float tv[16], cv[16];
    float st = 0.f, sc = 0.f;
#pragma unroll
    for (int i = 0; i < 16; i++) {
        int d = lane + i * 32;
        tv[i] = tr[d]; cv[i] = cr[d];
        st += tv[i] * tv[i]; sc += cv[i] * cv[i];
    }
    st = wsum(st); sc = wsum(sc);
    float rit = rsqrtf(st), ric = rsqrtf(sc);
    float av[16]; float sa = 0.f;
#pragma unroll
    for (int i = 0; i < 16; i++) { av[i] = tv[i] * rit + cv[i] * ric; sa += av[i] * av[i]; }
    sa = wsum(sa);
    float ra = rsqrtf(sa);
#pragma unroll
    for (int i = 0; i < 16; i++) {
        int d = lane + i * 32;
        out[(size_t)row * D_ + d] = av[i] * ra;
    }
}

// ------------------------- host orchestration -------------------------
static void gemmNT(const float* A, const float* B, const float* bias, float* C,
                   int M, int N, int K, int lda, int ldb, int ldc,
                   int Z = 1, int zsA = 0, int zsB = 0, int zsC = 0, int zsBias = 0,
                   bool relu = false)
{
    dim3 grid((N + 127) / 128, M / 128, Z);
    if (relu)
        gemm_kernel<true, true><<<grid, 256>>>(A, B, bias, C, M, N, K, lda, ldb, ldc, zsA, zsB, zsC, zsBias);
    else
        gemm_kernel<true, false><<<grid, 256>>>(A, B, bias, C, M, N, K, lda, ldb, ldc, zsA, zsB, zsC, zsBias);
}

static void gemmNN(const float* A, const float* B, const float* bias, float* C,
                   int M, int N, int K, int lda, int ldb, int ldc,
                   int Z = 1, int zsA = 0, int zsB = 0, int zsC = 0, int zsBias = 0)
{
    dim3 grid((N + 127) / 128, M / 128, Z);
    gemm_kernel<false, false><<<grid, 256>>>(A, B, bias, C, M, N, K, lda, ldb, ldc, zsA, zsB, zsC, zsBias);
}

extern "C" void kernel_launch(void* const* d_in, const int* in_sizes, int n_in,
                              void* d_out, int out_size)
{
    const float* x        = (const float*)d_in[0];
    const float* cf       = (const float*)d_in[1];
    const float* te       = (const float*)d_in[2];
    const float* pos      = (const float*)d_in[3];
    const float* ce       = (const float*)d_in[4];
    const float* sa_in_w  = (const float*)d_in[5];
    const float* sa_in_b  = (const float*)d_in[6];
    const float* sa_out_w = (const float*)d_in[7];
    const float* sa_out_b = (const float*)d_in[8];
    const float* ca_in_w  = (const float*)d_in[9];
    const float* ca_in_b  = (const float*)d_in[10];
    const float* ca_out_w = (const float*)d_in[11];
    const float* ca_out_b = (const float*)d_in[12];
    const float* lin1_w   = (const float*)d_in[13];
    const float* lin1_b   = (const float*)d_in[14];
    const float* lin2_w   = (const float*)d_in[15];
    const float* lin2_b   = (const float*)d_in[16];
    const float* ln1_g    = (const float*)d_in[17];
    const float* ln1_b    = (const float*)d_in[18];
    const float* ln2_g    = (const float*)d_in[19];
    const float* ln2_b    = (const float*)d_in[20];
    const float* ln3_g    = (const float*)d_in[21];
    const float* ln3_b    = (const float*)d_in[22];
    const float* region_w = (const float*)d_in[23];
    const float* region_b = (const float*)d_in[24];
    float* out = (float*)d_out;

    float *scores, *topv, *kvb, *tbuf, *qb, *ub, *cb, *ob, *buf1, *buf2, *buf3, *coarse;
    int* topi;
    cudaGetSymbolAddress((void**)&scores, g_scores);
    cudaGetSymbolAddress((void**)&topv,   g_topv);
    cudaGetSymbolAddress((void**)&topi,   g_topi);
    cudaGetSymbolAddress((void**)&kvb,    g_kv);
    cudaGetSymbolAddress((void**)&tbuf,   g_t);
    cudaGetSymbolAddress((void**)&qb,     g_q);
    cudaGetSymbolAddress((void**)&ub,     g_u);
    cudaGetSymbolAddress((void**)&cb,     g_c);
    cudaGetSymbolAddress((void**)&ob,     g_o);
    cudaGetSymbolAddress((void**)&buf1,   g_buf1);
    cudaGetSymbolAddress((void**)&buf2,   g_buf2);
    cudaGetSymbolAddress((void**)&buf3,   g_buf3);
    cudaGetSymbolAddress((void**)&coarse, g_coarse);

    cudaFuncSetAttribute(topk_kernel, cudaFuncAttributeMaxDynamicSharedMemorySize, 65536);
    const int attn_smem = (NKV * D_ + H_ * D_) * 4;
    cudaFuncSetAttribute(attn_kernel, cudaFuncAttributeMaxDynamicSharedMemorySize, attn_smem);

    // 1) concept scores + top-32 + KV assembly
    gemmNT(x, cf, nullptr, scores, B_, N_, D_, D_, D_, N_);
    topk_kernel<<<B_, 256, 65536>>>(scores, topv, topi);
    build_kv_kernel<<<B_, 256>>>(x, cf, te, pos, topv, topi, kvb);
    init_t_kernel<<<B_, D_>>>(tbuf, ce);

    const size_t DD = (size_t)D_ * D_;
    for (int i = 0; i < L_; i++) {
        const float* wv_sa = sa_in_w + i * 3 * DD + 2 * DD;
        const float* bv_sa = sa_in_b + i * 3 * D_ + 2 * D_;
        const float* wq    = ca_in_w + i * 3 * DD;
        const float* wk    = wq + DD;
        const float* wv    = wq + 2 * DD;
        const float* bq    = ca_in_b + i * 3 * D_;
        const float* bk    = bq + D_;
        const float* bv    = bq + 2 * D_;

        // --- self-attention over 1 token == two linear layers ---
        gemmNT(tbuf, wv_sa, bv_sa, buf2, B_, D_, D_, D_, D_, D_);
        gemmNT(buf2, sa_out_w + i * DD, sa_out_b + i * D_, buf3, B_, D_, D_, D_, D_, D_);
        add_ln_kernel<<<B_ / 8, 256>>>(tbuf, buf3, ln1_g + i * D_, ln1_b + i * D_);

        // --- cross-attention (factored: u = Wk_h^T q_h ; o_h = Wv_h c_h) ---
        gemmNT(tbuf, wq, bq, qb, B_, D_, D_, D_, D_, D_);
        gemmNN(qb, wk, nullptr, ub, B_, D_, HD_, D_, D_, H_ * D_,
               H_, HD_, HD_ * D_, D_, 0);
        attn_kernel<<<B_, 256, attn_smem>>>(qb, ub, kvb, bk, cb);
        gemmNT(cb, wv, bv, ob, B_, HD_, D_, H_ * D_, D_, D_,
               H_, D_, HD_ * D_, HD_, HD_);
        gemmNT(ob, ca_out_w + i * DD, ca_out_b + i * D_, buf3, B_, D_, D_, D_, D_, D_);
        add_ln_kernel<<<B_ / 8, 256>>>(tbuf, buf3, ln2_g + i * D_, ln2_b + i * D_);

        // --- feed-forward ---
        gemmNT(tbuf, lin1_w + (size_t)i * FF_ * D_, lin1_b + i * FF_, buf1,
               B_, FF_, D_, D_, D_, FF_, 1, 0, 0, 0, 0, true);
        gemmNT(buf1, lin2_w + (size_t)i * D_ * FF_, lin2_b + i * D_, buf3,
               B_, D_, FF_, FF_, FF_, D_);
        add_ln_kernel<<<B_ / 8, 256>>>(tbuf, buf3, ln3_g + i * D_, ln3_b + i * D_);
    }

    // 2) coarse branch + final combine
    gemmNT(x, region_w, region_b, coarse, B_, D_, D_, D_, D_, D_);
    final_kernel<<<B_ / 8, 256>>>(tbuf, coarse, out);
}

// round 11
// speedup vs baseline: 1.0058x; 1.0006x over previous
#include <cuda_runtime.h>
#include <math_constants.h>
#include <cstdint>

#define D_   512
#define K_   32
#define N_   50000
#define B_   4096
#define H_   8
#define FF_  2048
#define L_   6
#define HD_  64
#define NKV  33
#define EPS_ 1e-5f

// ------------------------- scratch (static device memory) -------------------------
__device__ float g_scores[(size_t)B_ * N_];        // 819 MB
__device__ float g_topv[B_ * K_];
__device__ int   g_topi[B_ * K_];
__device__ float g_kv[(size_t)B_ * NKV * D_];      // 277 MB
__device__ float g_t[B_ * D_];
__device__ float g_q[B_ * D_];
__device__ float g_u[(size_t)B_ * H_ * D_];        // 67 MB
__device__ float g_c[(size_t)B_ * H_ * D_];        // 67 MB
__device__ float g_o[B_ * D_];
__device__ float g_buf1[(size_t)B_ * FF_];         // 33.5 MB
__device__ float g_buf2[B_ * D_];
__device__ float g_buf3[B_ * D_];
__device__ float g_coarse[B_ * D_];

__device__ __forceinline__ float wsum(float v) {
#pragma unroll
    for (int o = 16; o; o >>= 1) v += __shfl_xor_sync(0xffffffffu, v, o);
    return v;
}

// ------------------------- generic fp32 tiled GEMM -------------------------
// C[M,N] = A[M,K] @ op(B) + bias, op(B) = B[N,K]^T (TRANSB) or B[K,N] (NN).
// blockIdx.z batches independent problems (per-head GEMMs) via zs* strides.
template <bool TRANSB, bool RELU>
__global__ void __launch_bounds__(256) gemm_kernel(
    const float* __restrict__ Ag, const float* __restrict__ Bg,
    const float* __restrict__ biasg, float* __restrict__ Cg,
    int M, int N, int K, int lda, int ldb, int ldc,
    int zsA, int zsB, int zsC, int zsBias)
{
    const float* A = Ag + (size_t)blockIdx.z * zsA;
    const float* B = Bg + (size_t)blockIdx.z * zsB;
    float* C = Cg + (size_t)blockIdx.z * zsC;

    __shared__ float As[16][128];
    __shared__ float Bs[16][128];

    const int n0 = blockIdx.x * 128;
    const int m0 = blockIdx.y * 128;
    const int tid = threadIdx.x;
    const int tx = tid & 15;
    const int ty = tid >> 4;

    float acc[8][8];
#pragma unroll
    for (int i = 0; i < 8; i++)
#pragma unroll
        for (int j = 0; j < 8; j++) acc[i][j] = 0.f;

    for (int k0 = 0; k0 < K; k0 += 16) {
#pragma unroll
        for (int l = 0; l < 2; l++) {
            int fidx = (tid + l * 256) * 4;
            int ar = fidx >> 4;
            int ac = fidx & 15;
            float4 v = *reinterpret_cast<const float4*>(A + (size_t)(m0 + ar) * lda + k0 + ac);
            As[ac + 0][ar] = v.x; As[ac + 1][ar] = v.y;
            As[ac + 2][ar] = v.z; As[ac + 3][ar] = v.w;
        }
        if (TRANSB) {
#pragma unroll
            for (int l = 0; l < 2; l++) {
                int fidx = (tid + l * 256) * 4;
                int br = fidx >> 4;   // n within tile
                int bc = fidx & 15;   // k within tile
                float4 v = make_float4(0.f, 0.f, 0.f, 0.f);
                if (n0 + br < N)
                    v = *reinterpret_cast<const float4*>(B + (size_t)(n0 + br) * ldb + k0 + bc);
                Bs[bc + 0][br] = v.x; Bs[bc + 1][br] = v.y;
                Bs[bc + 2][br] = v.z; Bs[bc + 3][br] = v.w;
            }
        } else {
#pragma unroll
            for (int l = 0; l < 2; l++) {
                int fidx = (tid + l * 256) * 4;
                int bk = fidx >> 7;   // k within tile
                int bn = fidx & 127;  // n within tile
                float4 v = make_float4(0.f, 0.f, 0.f, 0.f);
                if (n0 + bn < N)
                    v = *reinterpret_cast<const float4*>(B + (size_t)(k0 + bk) * ldb + n0 + bn);
                *reinterpret_cast<float4*>(&Bs[bk][bn]) = v;
            }
        }
        __syncthreads();
#pragma unroll
        for (int kk = 0; kk < 16; kk++) {
            float a[8], bb[8];
#pragma unroll
            for (int i = 0; i < 8; i++) a[i] = As[kk][ty * 8 + i];
#pragma unroll
            for (int j = 0; j < 8; j++) bb[j] = Bs[kk][tx * 8 + j];
#pragma unroll
            for (int i = 0; i < 8; i++)
#pragma unroll
                for (int j = 0; j < 8; j++) acc[i][j] = fmaf(a[i], bb[j], acc[i][j]);
        }
        __syncthreads();
    }

    const float* bias = biasg ? biasg + (size_t)blockIdx.z * zsBias : nullptr;
#pragma unroll
    for (int i = 0; i < 8; i++) {
        int m = m0 + ty * 8 + i;
#pragma unroll
        for (int j = 0; j < 8; j++) {
            int n = n0 + tx * 8 + j;
            if (n < N) {
                float v = acc[i][j];
                if (bias) v += bias[n];
                if (RELU) v = fmaxf(v, 0.f);
                C[(size_t)m * ldc + n] = v;
            }
        }
    }
}

// ------------------------- top-32 per row (descending, jax tie-break) -------------------------
__global__ void __launch_bounds__(256) topk_kernel(const float* __restrict__ scores,
                                                   float* __restrict__ topv,
                                                   int* __restrict__ topi)
{
    extern __shared__ float sm[];
    float* sv = sm;                   // 8192 floats
    int* si = (int*)(sm + 8192);      // 8192 ints
    __shared__ float rv[8];
    __shared__ int ri[8];
    __shared__ int rp[8];

    const int b = blockIdx.x;
    const int tid = threadIdx.x;
    const int lane = tid & 31, warp = tid >> 5;
    const float* row = scores + (size_t)b * N_;

    // per-thread local top-32 (sorted descending; stable -> lower index first on ties)
    float lv[32]; int li[32];
#pragma unroll
    for (int i = 0; i < 32; i++) { lv[i] = -CUDART_INF_F; li[i] = 0x7fffffff; }
    for (int j = tid; j < N_; j += 256) {
        float v = row[j];
        if (v > lv[31]) {
            int p = 31;
            while (p > 0 && lv[p - 1] < v) { lv[p] = lv[p - 1]; li[p] = li[p - 1]; p--; }
            lv[p] = v; li[p] = j;
        }
    }
#pragma unroll
    for (int i = 0; i < 32; i++) { sv[tid * 32 + i] = lv[i]; si[tid * 32 + i] = li[i]; }
    __syncthreads();

    // 32 rounds of block argmax over 8192 candidates
    for (int r = 0; r < 32; r++) {
        float bv = -CUDART_INF_F; int bi = 0x7fffffff; int bp = -1;
        for (int p = tid; p < 8192; p += 256) {
            float v = sv[p];
            int idx = si[p];
            if (v > bv || (v == bv && idx < bi)) { bv = v; bi = idx; bp = p; }
        }
#pragma unroll
        for (int o = 16; o; o >>= 1) {
            float ov = __shfl_xor_sync(0xffffffffu, bv, o);
            int oi = __shfl_xor_sync(0xffffffffu, bi, o);
            int op = __shfl_xor_sync(0xffffffffu, bp, o);
            if (ov > bv || (ov == bv && oi < bi)) { bv = ov; bi = oi; bp = op; }
        }
        if (lane == 0) { rv[warp] = bv; ri[warp] = bi; rp[warp] = bp; }
        __syncthreads();
        if (tid == 0) {
            float fbv = rv[0]; int fbi = ri[0]; int fbp = rp[0];
#pragma unroll
            for (int w = 1; w < 8; w++)
                if (rv[w] > fbv || (rv[w] == fbv && ri[w] < fbi)) { fbv = rv[w]; fbi = ri[w]; fbp = rp[w]; }
            topv[b * 32 + r] = fbv;
            topi[b * 32 + r] = fbi;
            sv[fbp] = -CUDART_INF_F;
        }
        __syncthreads();
    }
}

// ------------------------- build KV: [x+te0 ; w*h_r + pos + te1] -------------------------
__global__ void __launch_bounds__(256) build_kv_kernel(
    const float* __restrict__ x, const float* __restrict__ cf,
    const float* __restrict__ te, const float* __restrict__ pos,
    const float* __restrict__ topv, const int* __restrict__ topi,
    float* __restrict__ kv)
{
    const int b = blockIdx.x;
    const int tid = threadIdx.x;
    __shared__ float w[32];
    if (tid < 32) {
        float m = topv[b * 32];               // sorted descending -> element 0 is the max
        float e = expf(topv[b * 32 + tid] - m);
        float s = e;
#pragma unroll
        for (int o = 16; o; o >>= 1) s += __shfl_xor_sync(0xffffffffu, s, o);
        w[tid] = e / s;
    }
    __syncthreads();
    float* kvb = kv + (size_t)b * NKV * D_;
    const float* xb = x + (size_t)b * D_;
    for (int d = tid; d < D_; d += 256) kvb[d] = xb[d] + te[d];
    for (int j = 0; j < 32; j++) {
        const float* h = cf + (size_t)topi[b * 32 + j] * D_;
        const float* pj = pos + j * D_;
        float wj = w[j];
        float* dst = kvb + (size_t)(j + 1) * D_;
        for (int d = tid; d < D_; d += 256) dst[d] = wj * h[d] + pj[d] + te[D_ + d];
    }
}

__global__ void init_t_kernel(float* __restrict__ t, const float* __restrict__ ce)
{
    t[(size_t)blockIdx.x * D_ + threadIdx.x] = ce[threadIdx.x];
}

// ------------------------- fused cross-attention core (per batch element) -------------------------
// logits_{h,j} = scale * ( u_h . kv_j + q_h . bk_h );  c_h = sum_j softmax_j * kv_j
__global__ void __launch_bounds__(256) attn_kernel(
    const float* __restrict__ q, const float* __restrict__ u,
    const float* __restrict__ kv, const float* __restrict__ bk,
    float* __restrict__ c)
{
    extern __shared__ float sm[];
    float* skv = sm;                  // NKV*D_
    float* su = sm + NKV * D_;        // H_*D_
    __shared__ float sq[D_];
    __shared__ float slog[H_ * NKV];
    __shared__ float sprob[H_ * NKV];
    __shared__ float sbeta[H_];

    const int b = blockIdx.x;
    const int tid = threadIdx.x;
    const int warp = tid >> 5, lane = tid & 31;

    const float* kvb = kv + (size_t)b * NKV * D_;
    const float* ub = u + (size_t)b * H_ * D_;
    const float* qb = q + (size_t)b * D_;
    for (int i = tid; i < NKV * D_; i += 256) skv[i] = kvb[i];
    for (int i = tid; i < H_ * D_; i += 256) su[i] = ub[i];
    for (int i = tid; i < D_; i += 256) sq[i] = qb[i];
    __syncthreads();

    { // beta_h = q_h . bk_h   (warp w -> head w)
        int h = warp;
        float s = sq[h * HD_ + lane] * bk[h * HD_ + lane]
                + sq[h * HD_ + 32 + lane] * bk[h * HD_ + 32 + lane];
        s = wsum(s);
        if (lane == 0) sbeta[h] = s;
    }
    __syncthreads();

    const float scale = 0.125f; // 1/sqrt(64)
    for (int p = warp; p < H_ * NKV; p += 8) {
        int h = p / NKV, j = p % NKV;
        const float* uh = su + h * D_;
        const float* kj = skv + j * D_;
        float s = 0.f;
#pragma unroll
        for (int d = lane; d < D_; d += 32) s += uh[d] * kj[d];
        s = wsum(s);
        if (lane == 0) slog[p] = (s + sbeta[h]) * scale;
    }
    __syncthreads();

    { // softmax over 33 keys, warp w -> head w
        int h = warp;
        float v0 = slog[h * NKV + lane];
        float v1 = (lane == 0) ? slog[h * NKV + 32] : -CUDART_INF_F;
        float m = fmaxf(v0, v1);
#pragma unroll
        for (int o = 16; o; o >>= 1) m = fmaxf(m, __shfl_xor_sync(0xffffffffu, m, o));
        float e0 = expf(v0 - m);
        float e1 = (lane == 0) ? expf(v1 - m) : 0.f;
        float s = wsum(e0 + e1);
        float inv = 1.f / s;
        sprob[h * NKV + lane] = e0 * inv;
        if (lane == 0) sprob[h * NKV + 32] = e1 * inv;
    }
    __syncthreads();

    float* cbp = c + (size_t)b * H_ * D_;
#pragma unroll
    for (int h = 0; h < H_; h++) {
        const float* pr = sprob + h * NKV;
        for (int d = tid; d < D_; d += 256) {
            float s = 0.f;
#pragma unroll
            for (int j = 0; j < NKV; j++) s += pr[j] * skv[j * D_ + d];
            cbp[h * D_ + d] = s;
        }
    }
}

// ------------------------- fused residual-add + LayerNorm (warp per row) -------------------------
__global__ void __launch_bounds__(256) add_ln_kernel(
    float* __restrict__ t, const float* __restrict__ r,
    const float* __restrict__ g, const float* __restrict__ bta)
{
    const int row = blockIdx.x * 8 + (threadIdx.x >> 5);
    const int lane = threadIdx.x & 31;
    float* tr = t + (size_t)row * D_;
    const float* rr = r + (size_t)row * D_;
    float v[16];
    float s = 0.f;
#pragma unroll
    for (int i = 0; i < 16; i++) { int d = lane + i * 32; v[i] = tr[d] + rr[d]; s += v[i]; }
    s = wsum(s);
    float mean = s * (1.f / D_);
    float s2 = 0.f;
#pragma unroll
    for (int i = 0; i < 16; i++) { float dd = v[i] - mean; s2 += dd * dd; }
    s2 = wsum(s2);
    float inv = rsqrtf(s2 * (1.f / D_) + EPS_);
#pragma unroll
    for (int i = 0; i < 16; i++) {
        int d = lane + i * 32;
        tr[d] = (v[i] - mean) * inv * g[d] + bta[d];
    }
}

// ------------------------- final: normalize(normalize(t) + normalize(coarse)) -------------------------
__global__ void __launch_bounds__(256) final_kernel(
    const float* __restrict__ t, const float* __restrict__ coarse,
    float* __restrict__ out)
{
    const int row = blockIdx.x * 8 + (threadIdx.x >> 5);
    const int lane = threadIdx.x & 31;
    const float* tr = t + (size_t)row * D_;
    const float* cr = coarse + (size_t)row * D_;
    float tv[16], cv[16];
    float st = 0.f, sc = 0.f;
#pragma unroll
    for (int i = 0; i < 16; i++) {
        int d = lane + i * 32;
        tv[i] = tr[d]; cv[i] = cr[d];
        st += tv[i] * tv[i]; sc += cv[i] * cv[i];
    }
    st = wsum(st); sc = wsum(sc);
    float rit = rsqrtf(st), ric = rsqrtf(sc);
    float av[16]; float sa = 0.f;
#pragma unroll
    for (int i = 0; i < 16; i++) { av[i] = tv[i] * rit + cv[i] * ric; sa += av[i] * av[i]; }
    sa = wsum(sa);
    float ra = rsqrtf(sa);
#pragma unroll
    for (int i = 0; i < 16; i++) {
        int d = lane + i * 32;
        out[(size_t)row * D_ + d] = av[i] * ra;
    }
}

// ------------------------- host orchestration -------------------------
static void gemmNT(const float* A, const float* B, const float* bias, float* C,
                   int M, int N, int K, int lda, int ldb, int ldc,
                   int Z = 1, int zsA = 0, int zsB = 0, int zsC = 0, int zsBias = 0,
                   bool relu = false)
{
    dim3 grid((N + 127) / 128, M / 128, Z);
    if (relu)
        gemm_kernel<true, true><<<grid, 256>>>(A, B, bias, C, M, N, K, lda, ldb, ldc, zsA, zsB, zsC, zsBias);
    else
        gemm_kernel<true, false><<<grid, 256>>>(A, B, bias, C, M, N, K, lda, ldb, ldc, zsA, zsB, zsC, zsBias);
}

static void gemmNN(const float* A, const float* B, const float* bias, float* C,
                   int M, int N, int K, int lda, int ldb, int ldc,
                   int Z = 1, int zsA = 0, int zsB = 0, int zsC = 0, int zsBias = 0)
{
    dim3 grid((N + 127) / 128, M / 128, Z);
    gemm_kernel<false, false><<<grid, 256>>>(A, B, bias, C, M, N, K, lda, ldb, ldc, zsA, zsB, zsC, zsBias);
}

extern "C" void kernel_launch(void* const* d_in, const int* in_sizes, int n_in,
                              void* d_out, int out_size)
{
    const float* x        = (const float*)d_in[0];
    const float* cf       = (const float*)d_in[1];
    const float* te       = (const float*)d_in[2];
    const float* pos      = (const float*)d_in[3];
    const float* ce       = (const float*)d_in[4];
    const float* sa_in_w  = (const float*)d_in[5];
    const float* sa_in_b  = (const float*)d_in[6];
    const float* sa_out_w = (const float*)d_in[7];
    const float* sa_out_b = (const float*)d_in[8];
    const float* ca_in_w  = (const float*)d_in[9];
    const float* ca_in_b  = (const float*)d_in[10];
    const float* ca_out_w = (const float*)d_in[11];
    const float* ca_out_b = (const float*)d_in[12];
    const float* lin1_w   = (const float*)d_in[13];
    const float* lin1_b   = (const float*)d_in[14];
    const float* lin2_w   = (const float*)d_in[15];
    const float* lin2_b   = (const float*)d_in[16];
    const float* ln1_g    = (const float*)d_in[17];
    const float* ln1_b    = (const float*)d_in[18];
    const float* ln2_g    = (const float*)d_in[19];
    const float* ln2_b    = (const float*)d_in[20];
    const float* ln3_g    = (const float*)d_in[21];
    const float* ln3_b    = (const float*)d_in[22];
    const float* region_w = (const float*)d_in[23];
    const float* region_b = (const float*)d_in[24];
    float* out = (float*)d_out;

    float *scores, *topv, *kvb, *tbuf, *qb, *ub, *cb, *ob, *buf1, *buf2, *buf3, *coarse;
    int* topi;
    cudaGetSymbolAddress((void**)&scores, g_scores);
    cudaGetSymbolAddress((void**)&topv,   g_topv);
    cudaGetSymbolAddress((void**)&topi,   g_topi);
    cudaGetSymbolAddress((void**)&kvb,    g_kv);
    cudaGetSymbolAddress((void**)&tbuf,   g_t);
    cudaGetSymbolAddress((void**)&qb,     g_q);
    cudaGetSymbolAddress((void**)&ub,     g_u);
    cudaGetSymbolAddress((void**)&cb,     g_c);
    cudaGetSymbolAddress((void**)&ob,     g_o);
    cudaGetSymbolAddress((void**)&buf1,   g_buf1);
    cudaGetSymbolAddress((void**)&buf2,   g_buf2);
    cudaGetSymbolAddress((void**)&buf3,   g_buf3);
    cudaGetSymbolAddress((void**)&coarse, g_coarse);

    cudaFuncSetAttribute(topk_kernel, cudaFuncAttributeMaxDynamicSharedMemorySize, 65536);
    const int attn_smem = (NKV * D_ + H_ * D_) * 4;
    cudaFuncSetAttribute(attn_kernel, cudaFuncAttributeMaxDynamicSharedMemorySize, attn_smem);

    // 1) concept scores + top-32 + KV assembly
    gemmNT(x, cf, nullptr, scores, B_, N_, D_, D_, D_, N_);
    topk_kernel<<<B_, 256, 65536>>>(scores, topv, topi);
    build_kv_kernel<<<B_, 256>>>(x, cf, te, pos, topv, topi, kvb);
    init_t_kernel<<<B_, D_>>>(tbuf, ce);

    const size_t DD = (size_t)D_ * D_;
    for (int i = 0; i < L_; i++) {
        const float* wv_sa = sa_in_w + i * 3 * DD + 2 * DD;
        const float* bv_sa = sa_in_b + i * 3 * D_ + 2 * D_;
        const float* wq    = ca_in_w + i * 3 * DD;
        const float* wk    = wq + DD;
        const float* wv    = wq + 2 * DD;
        const float* bq    = ca_in_b + i * 3 * D_;
        const float* bk    = bq + D_;
        const float* bv    = bq + 2 * D_;

        // --- self-attention over 1 token == two linear layers ---
        gemmNT(tbuf, wv_sa, bv_sa, buf2, B_, D_, D_, D_, D_, D_);
        gemmNT(buf2, sa_out_w + i * DD, sa_out_b + i * D_, buf3, B_, D_, D_, D_, D_, D_);
        add_ln_kernel<<<B_ / 8, 256>>>(tbuf, buf3, ln1_g + i * D_, ln1_b + i * D_);

        // --- cross-attention (factored: u = Wk_h^T q_h ; o_h = Wv_h c_h) ---
        gemmNT(tbuf, wq, bq, qb, B_, D_, D_, D_, D_, D_);
        gemmNN(qb, wk, nullptr, ub, B_, D_, HD_, D_, D_, H_ * D_,
               H_, HD_, HD_ * D_, D_, 0);
        attn_kernel<<<B_, 256, attn_smem>>>(qb, ub, kvb, bk, cb);
        gemmNT(cb, wv, bv, ob, B_, HD_, D_, H_ * D_, D_, D_,
               H_, D_, HD_ * D_, HD_, HD_);
        gemmNT(ob, ca_out_w + i * DD, ca_out_b + i * D_, buf3, B_, D_, D_, D_, D_, D_);
        add_ln_kernel<<<B_ / 8, 256>>>(tbuf, buf3, ln2_g + i * D_, ln2_b + i * D_);

        // --- feed-forward ---
        gemmNT(tbuf, lin1_w + (size_t)i * FF_ * D_, lin1_b + i * FF_, buf1,
               B_, FF_, D_, D_, D_, FF_, 1, 0, 0, 0, 0, true);
        gemmNT(buf1, lin2_w + (size_t)i * D_ * FF_, lin2_b + i * D_, buf3,
               B_, D_, FF_, FF_, FF_, D_);
        add_ln_kernel<<<B_ / 8, 256>>>(tbuf, buf3, ln3_g + i * D_, ln3_b + i * D_);
    }

    // 2) coarse branch + final combine
    gemmNT(x, region_w, region_b, coarse, B_, D_, D_, D_, D_, D_);
    final_kernel<<<B_ / 8, 256>>>(tbuf, coarse, out);
}

// round 12
// speedup vs baseline: 1.0070x; 1.0012x over previous
#include <cuda_runtime.h>
#include <math_constants.h>
#include <cstdint>

#define D_   512
#define K_   32
#define N_   50000
#define B_   4096
#define H_   8
#define FF_  2048
#define L_   6
#define HD_  64
#define NKV  33
#define EPS_ 1e-5f

// ------------------------- scratch (static device memory) -------------------------
__device__ float g_scores[(size_t)B_ * N_];        // 819 MB
__device__ float g_topv[B_ * K_];
__device__ int   g_topi[B_ * K_];
__device__ float g_kv[(size_t)B_ * NKV * D_];      // 277 MB
__device__ float g_t[B_ * D_];
__device__ float g_q[B_ * D_];
__device__ float g_u[(size_t)B_ * H_ * D_];        // 67 MB
__device__ float g_c[(size_t)B_ * H_ * D_];        // 67 MB
__device__ float g_o[B_ * D_];
__device__ float g_buf1[(size_t)B_ * FF_];         // 33.5 MB
__device__ float g_buf2[B_ * D_];
__device__ float g_buf3[B_ * D_];
__device__ float g_coarse[B_ * D_];

__device__ __forceinline__ float wsum(float v) {
#pragma unroll
    for (int o = 16; o; o >>= 1) v += __shfl_xor_sync(0xffffffffu, v, o);
    return v;
}

// ------------------------- generic fp32 tiled GEMM -------------------------
// C[M,N] = A[M,K] @ op(B) + bias, op(B) = B[N,K]^T (TRANSB) or B[K,N] (NN).
// blockIdx.z batches independent problems (per-head GEMMs) via zs* strides.
template <bool TRANSB, bool RELU>
__global__ void __launch_bounds__(256) gemm_kernel(
    const float* __restrict__ Ag, const float* __restrict__ Bg,
    const float* __restrict__ biasg, float* __restrict__ Cg,
    int M, int N, int K, int lda, int ldb, int ldc,
    int zsA, int zsB, int zsC, int zsBias)
{
    const float* A = Ag + (size_t)blockIdx.z * zsA;
    const float* B = Bg + (size_t)blockIdx.z * zsB;
    float* C = Cg + (size_t)blockIdx.z * zsC;

    __shared__ float As[16][128];
    __shared__ float Bs[16][128];

    const int n0 = blockIdx.x * 128;
    const int m0 = blockIdx.y * 128;
    const int tid = threadIdx.x;
    const int tx = tid & 15;
    const int ty = tid >> 4;

    float acc[8][8];
#pragma unroll
    for (int i = 0; i < 8; i++)
#pragma unroll
        for (int j = 0; j < 8; j++) acc[i][j] = 0.f;

    for (int k0 = 0; k0 < K; k0 += 16) {
#pragma unroll
        for (int l = 0; l < 2; l++) {
            int fidx = (tid + l * 256) * 4;
            int ar = fidx >> 4;
            int ac = fidx & 15;
            float4 v = *reinterpret_cast<const float4*>(A + (size_t)(m0 + ar) * lda + k0 + ac);
            As[ac + 0][ar] = v.x; As[ac + 1][ar] = v.y;
            As[ac + 2][ar] = v.z; As[ac + 3][ar] = v.w;
        }
        if (TRANSB) {
#pragma unroll
            for (int l = 0; l < 2; l++) {
                int fidx = (tid + l * 256) * 4;
                int br = fidx >> 4;   // n within tile
                int bc = fidx & 15;   // k within tile
                float4 v = make_float4(0.f, 0.f, 0.f, 0.f);
                if (n0 + br < N)
                    v = *reinterpret_cast<const float4*>(B + (size_t)(n0 + br) * ldb + k0 + bc);
                Bs[bc + 0][br] = v.x; Bs[bc + 1][br] = v.y;
                Bs[bc + 2][br] = v.z; Bs[bc + 3][br] = v.w;
            }
        } else {
#pragma unroll
            for (int l = 0; l < 2; l++) {
                int fidx = (tid + l * 256) * 4;
                int bk = fidx >> 7;   // k within tile
                int bn = fidx & 127;  // n within tile
                float4 v = make_float4(0.f, 0.f, 0.f, 0.f);
                if (n0 + bn < N)
                    v = *reinterpret_cast<const float4*>(B + (size_t)(k0 + bk) * ldb + n0 + bn);
                *reinterpret_cast<float4*>(&Bs[bk][bn]) = v;
            }
        }
        __syncthreads();
#pragma unroll
        for (int kk = 0; kk < 16; kk++) {
            float a[8], bb[8];
#pragma unroll
            for (int i = 0; i < 8; i++) a[i] = As[kk][ty * 8 + i];
#pragma unroll
            for (int j = 0; j < 8; j++) bb[j] = Bs[kk][tx * 8 + j];
#pragma unroll
            for (int i = 0; i < 8; i++)
#pragma unroll
                for (int j = 0; j < 8; j++) acc[i][j] = fmaf(a[i], bb[j], acc[i][j]);
        }
        __syncthreads();
    }

    const float* bias = biasg ? biasg + (size_t)blockIdx.z * zsBias : nullptr;
#pragma unroll
    for (int i = 0; i < 8; i++) {
        int m = m0 + ty * 8 + i;
#pragma unroll
        for (int j = 0; j < 8; j++) {
            int n = n0 + tx * 8 + j;
            if (n < N) {
                float v = acc[i][j];
                if (bias) v += bias[n];
                if (RELU) v = fmaxf(v, 0.f);
                C[(size_t)m * ldc + n] = v;
            }
        }
    }
}

// ------------------------- top-32 per row (descending, jax tie-break) -------------------------
__global__ void __launch_bounds__(256) topk_kernel(const float* __restrict__ scores,
                                                   float* __restrict__ topv,
                                                   int* __restrict__ topi)
{
    extern __shared__ float sm[];
    float* sv = sm;                   // 8192 floats
    int* si = (int*)(sm + 8192);      // 8192 ints
    __shared__ float rv[8];
    __shared__ int ri[8];
    __shared__ int rp[8];

    const int b = blockIdx.x;
    const int tid = threadIdx.x;
    const int lane = tid & 31, warp = tid >> 5;
    const float* row = scores + (size_t)b * N_;

    // per-thread local top-32 (sorted descending; stable -> lower index first on ties)
    float lv[32]; int li[32];
#pragma unroll
    for (int i = 0; i < 32; i++) { lv[i] = -CUDART_INF_F; li[i] = 0x7fffffff; }
    for (int j = tid; j < N_; j += 256) {
        float v = row[j];
        if (v > lv[31]) {
            int p = 31;
            while (p > 0 && lv[p - 1] < v) { lv[p] = lv[p - 1]; li[p] = li[p - 1]; p--; }
            lv[p] = v; li[p] = j;
        }
    }
#pragma unroll
    for (int i = 0; i < 32; i++) { sv[tid * 32 + i] = lv[i]; si[tid * 32 + i] = li[i]; }
    __syncthreads();

    // 32 rounds of block argmax over 8192 candidates
    for (int r = 0; r < 32; r++) {
        float bv = -CUDART_INF_F; int bi = 0x7fffffff; int bp = -1;
        for (int p = tid; p < 8192; p += 256) {
            float v = sv[p];
            int idx = si[p];
            if (v > bv || (v == bv && idx < bi)) { bv = v; bi = idx; bp = p; }
        }
#pragma unroll
        for (int o = 16; o; o >>= 1) {
            float ov = __shfl_xor_sync(0xffffffffu, bv, o);
            int oi = __shfl_xor_sync(0xffffffffu, bi, o);
            int op = __shfl_xor_sync(0xffffffffu, bp, o);
            if (ov > bv || (ov == bv && oi < bi)) { bv = ov; bi = oi; bp = op; }
        }
        if (lane == 0) { rv[warp] = bv; ri[warp] = bi; rp[warp] = bp; }
        __syncthreads();
        if (tid == 0) {
            float fbv = rv[0]; int fbi = ri[0]; int fbp = rp[0];
#pragma unroll
            for (int w = 1; w < 8; w++)
                if (rv[w] > fbv || (rv[w] == fbv && ri[w] < fbi)) { fbv = rv[w]; fbi = ri[w]; fbp = rp[w]; }
            topv[b * 32 + r] = fbv;
            topi[b * 32 + r] = fbi;
            sv[fbp] = -CUDART_INF_F;
        }
        __syncthreads();
    }
}

// ------------------------- build KV: [x+te0 ; w*h_r + pos + te1] -------------------------
__global__ void __launch_bounds__(256) build_kv_kernel(
    const float* __restrict__ x, const float* __restrict__ cf,
    const float* __restrict__ te, const float* __restrict__ pos,
    const float* __restrict__ topv, const int* __restrict__ topi,
    float* __restrict__ kv)
{
    const int b = blockIdx.x;
    const int tid = threadIdx.x;
    __shared__ float w[32];
    if (tid < 32) {
        float m = topv[b * 32];               // sorted descending -> element 0 is the max
        float e = expf(topv[b * 32 + tid] - m);
        float s = e;
#pragma unroll
        for (int o = 16; o; o >>= 1) s += __shfl_xor_sync(0xffffffffu, s, o);
        w[tid] = e / s;
    }
    __syncthreads();
    float* kvb = kv + (size_t)b * NKV * D_;
    const float* xb = x + (size_t)b * D_;
    for (int d = tid; d < D_; d += 256) kvb[d] = xb[d] + te[d];
    for (int j = 0; j < 32; j++) {
        const float* h = cf + (size_t)topi[b * 32 + j] * D_;
        const float* pj = pos + j * D_;
        float wj = w[j];
        float* dst = kvb + (size_t)(j + 1) * D_;
        for (int d = tid; d < D_; d += 256) dst[d] = wj * h[d] + pj[d] + te[D_ + d];
    }
}

__global__ void init_t_kernel(float* __restrict__ t, const float* __restrict__ ce)
{
    t[(size_t)blockIdx.x * D_ + threadIdx.x] = ce[threadIdx.x];
}

// ------------------------- fused cross-attention core (per batch element) -------------------------
// logits_{h,j} = scale * ( u_h . kv_j + q_h . bk_h );  c_h = sum_j softmax_j * kv_j
__global__ void __launch_bounds__(256) attn_kernel(
    const float* __restrict__ q, const float* __restrict__ u,
    const float* __restrict__ kv, const float* __restrict__ bk,
    float* __restrict__ c)
{
    extern __shared__ float sm[];
    float* skv = sm;                  // NKV*D_
    float* su = sm + NKV * D_;        // H_*D_
    __shared__ float sq[D_];
    __shared__ float slog[H_ * NKV];
    __shared__ float sprob[H_ * NKV];
    __shared__ float sbeta[H_];

    const int b = blockIdx.x;
    const int tid = threadIdx.x;
    const int warp = tid >> 5, lane = tid & 31;

    const float* kvb = kv + (size_t)b * NKV * D_;
    const float* ub = u + (size_t)b * H_ * D_;
    const float* qb = q + (size_t)b * D_;
    for (int i = tid; i < NKV * D_; i += 256) skv[i] = kvb[i];
    for (int i = tid; i < H_ * D_; i += 256) su[i] = ub[i];
    for (int i = tid; i < D_; i += 256) sq[i] = qb[i];
    __syncthreads();

    { // beta_h = q_h . bk_h   (warp w -> head w)
        int h = warp;
        float s = sq[h * HD_ + lane] * bk[h * HD_ + lane]
                + sq[h * HD_ + 32 + lane] * bk[h * HD_ + 32 + lane];
        s = wsum(s);
        if (lane == 0) sbeta[h] = s;
    }
    __syncthreads();

    const float scale = 0.125f; // 1/sqrt(64)
    for (int p = warp; p < H_ * NKV; p += 8) {
        int h = p / NKV, j = p % NKV;
        const float* uh = su + h * D_;
        const float* kj = skv + j * D_;
        float s = 0.f;
#pragma unroll
        for (int d = lane; d < D_; d += 32) s += uh[d] * kj[d];
        s = wsum(s);
        if (lane == 0) slog[p] = (s + sbeta[h]) * scale;
    }
    __syncthreads();

    { // softmax over 33 keys, warp w -> head w
        int h = warp;
        float v0 = slog[h * NKV + lane];
        float v1 = (lane == 0) ? slog[h * NKV + 32] : -CUDART_INF_F;
        float m = fmaxf(v0, v1);
#pragma unroll
        for (int o = 16; o; o >>= 1) m = fmaxf(m, __shfl_xor_sync(0xffffffffu, m, o));
        float e0 = expf(v0 - m);
        float e1 = (lane == 0) ? expf(v1 - m) : 0.f;
        float s = wsum(e0 + e1);
        float inv = 1.f / s;
        sprob[h * NKV + lane] = e0 * inv;
        if (lane == 0) sprob[h * NKV + 32] = e1 * inv;
    }
    __syncthreads();

    float* cbp = c + (size_t)b * H_ * D_;
#pragma unroll
    for (int h = 0; h < H_; h++) {
        const float* pr = sprob + h * NKV;
        for (int d = tid; d < D_; d += 256) {
            float s = 0.f;
#pragma unroll
            for (int j = 0; j < NKV; j++) s += pr[j] * skv[j * D_ + d];
            cbp[h * D_ + d] = s;
        }
    }
}

// ------------------------- fused residual-add + LayerNorm (warp per row) -------------------------
__global__ void __launch_bounds__(256) add_ln_kernel(
    float* __restrict__ t, const float* __restrict__ r,
    const float* __restrict__ g, const float* __restrict__ bta)
{
    const int row = blockIdx.x * 8 + (threadIdx.x >> 5);
    const int lane = threadIdx.x & 31;
    float* tr = t + (size_t)row * D_;
    const float* rr = r + (size_t)row * D_;
    float v[16];
    float s = 0.f;
#pragma unroll
    for (int i = 0; i < 16; i++) { int d = lane + i * 32; v[i] = tr[d] + rr[d]; s += v[i]; }
    s = wsum(s);
    float mean = s * (1.f / D_);
    float s2 = 0.f;
#pragma unroll
    for (int i = 0; i < 16; i++) { float dd = v[i] - mean; s2 += dd * dd; }
    s2 = wsum(s2);
    float inv = rsqrtf(s2 * (1.f / D_) + EPS_);
#pragma unroll
    for (int i = 0; i < 16; i++) {
        int d = lane + i * 32;
        tr[d] = (v[i] - mean) * inv * g[d] + bta[d];
    }
}

// ------------------------- final: normalize(normalize(t) + normalize(coarse)) -------------------------
__global__ void __launch_bounds__(256) final_kernel(
    const float* __restrict__ t, const float* __restrict__ coarse,
    float* __restrict__ out)
{
    const int row = blockIdx.x * 8 + (threadIdx.x >> 5);
    const int lane = threadIdx.x & 31;
    const float* tr = t + (size_t)row * D_;
    const float* cr = coarse + (size_t)row * D_;
    float tv[16], cv[16];
    float st = 0.f, sc = 0.f;
#pragma unroll
    for (int i = 0; i < 16; i++) {
        int d = lane + i * 32;
        tv[i] = tr[d]; cv[i] = cr[d];
        st += tv[i] * tv[i]; sc += cv[i] * cv[i];
    }
    st = wsum(st); sc = wsum(sc);
    float rit = rsqrtf(st), ric = rsqrtf(sc);
    float av[16]; float sa = 0.f;
#pragma unroll
    for (int i = 0; i < 16; i++) { av[i] = tv[i] * rit + cv[i] * ric; sa += av[i] * av[i]; }
    sa = wsum(sa);
    float ra = rsqrtf(sa);
#pragma unroll
    for (int i = 0; i < 16; i++) {
        int d = lane + i * 32;
        out[(size_t)row * D_ + d] = av[i] * ra;
    }
}

// ------------------------- host orchestration -------------------------
static void gemmNT(const float* A, const float* B, const float* bias, float* C,
                   int M, int N, int K, int lda, int ldb, int ldc,
                   int Z = 1, int zsA = 0, int zsB = 0, int zsC = 0, int zsBias = 0,
                   bool relu = false)
{
    dim3 grid((N + 127) / 128, M / 128, Z);
    if (relu)
        gemm_kernel<true, true><<<grid, 256>>>(A, B, bias, C, M, N, K, lda, ldb, ldc, zsA, zsB, zsC, zsBias);
    else
        gemm_kernel<true, false><<<grid, 256>>>(A, B, bias, C, M, N, K, lda, ldb, ldc, zsA, zsB, zsC, zsBias);
}

static void gemmNN(const float* A, const float* B, const float* bias, float* C,
                   int M, int N, int K, int lda, int ldb, int ldc,
                   int Z = 1, int zsA = 0, int zsB = 0, int zsC = 0, int zsBias = 0)
{
    dim3 grid((N + 127) / 128, M / 128, Z);
    gemm_kernel<false, false><<<grid, 256>>>(A, B, bias, C, M, N, K, lda, ldb, ldc, zsA, zsB, zsC, zsBias);
}

extern "C" void kernel_launch(void* const* d_in, const int* in_sizes, int n_in,
                              void* d_out, int out_size)
{
    const float* x        = (const float*)d_in[0];
    const float* cf       = (const float*)d_in[1];
    const float* te       = (const float*)d_in[2];
    const float* pos      = (const float*)d_in[3];
    const float* ce       = (const float*)d_in[4];
    const float* sa_in_w  = (const float*)d_in[5];
    const float* sa_in_b  = (const float*)d_in[6];
    const float* sa_out_w = (const float*)d_in[7];
    const float* sa_out_b = (const float*)d_in[8];
    const float* ca_in_w  = (const float*)d_in[9];
    const float* ca_in_b  = (const float*)d_in[10];
    const float* ca_out_w = (const float*)d_in[11];
    const float* ca_out_b = (const float*)d_in[12];
    const float* lin1_w   = (const float*)d_in[13];
    const float* lin1_b   = (const float*)d_in[14];
    const float* lin2_w   = (const float*)d_in[15];
    const float* lin2_b   = (const float*)d_in[16];
    const float* ln1_g    = (const float*)d_in[17];
    const float* ln1_b    = (const float*)d_in[18];
    const float* ln2_g    = (const float*)d_in[19];
    const float* ln2_b    = (const float*)d_in[20];
    const float* ln3_g    = (const float*)d_in[21];
    const float* ln3_b    = (const float*)d_in[22];
    const float* region_w = (const float*)d_in[23];
    const float* region_b = (const float*)d_in[24];
    float* out = (float*)d_out;

    float *scores, *topv, *kvb, *tbuf, *qb, *ub, *cb, *ob, *buf1, *buf2, *buf3, *coarse;
    int* topi;
    cudaGetSymbolAddress((void**)&scores, g_scores);
    cudaGetSymbolAddress((void**)&topv,   g_topv);
    cudaGetSymbolAddress((void**)&topi,   g_topi);
    cudaGetSymbolAddress((void**)&kvb,    g_kv);
    cudaGetSymbolAddress((void**)&tbuf,   g_t);
    cudaGetSymbolAddress((void**)&qb,     g_q);
    cudaGetSymbolAddress((void**)&ub,     g_u);
    cudaGetSymbolAddress((void**)&cb,     g_c);
    cudaGetSymbolAddress((void**)&ob,     g_o);
    cudaGetSymbolAddress((void**)&buf1,   g_buf1);
    cudaGetSymbolAddress((void**)&buf2,   g_buf2);
    cudaGetSymbolAddress((void**)&buf3,   g_buf3);
    cudaGetSymbolAddress((void**)&coarse, g_coarse);

    cudaFuncSetAttribute(topk_kernel, cudaFuncAttributeMaxDynamicSharedMemorySize, 65536);
    const int attn_smem = (NKV * D_ + H_ * D_) * 4;
    cudaFuncSetAttribute(attn_kernel, cudaFuncAttributeMaxDynamicSharedMemorySize, attn_smem);

    // 1) concept scores + top-32 + KV assembly
    gemmNT(x, cf, nullptr, scores, B_, N_, D_, D_, D_, N_);
    topk_kernel<<<B_, 256, 65536>>>(scores, topv, topi);
    build_kv_kernel<<<B_, 256>>>(x, cf, te, pos, topv, topi, kvb);
    init_t_kernel<<<B_, D_>>>(tbuf, ce);

    const size_t DD = (size_t)D_ * D_;
    for (int i = 0; i < L_; i++) {
        const float* wv_sa = sa_in_w + i * 3 * DD + 2 * DD;
        const float* bv_sa = sa_in_b + i * 3 * D_ + 2 * D_;
        const float* wq    = ca_in_w + i * 3 * DD;
        const float* wk    = wq + DD;
        const float* wv    = wq + 2 * DD;
        const float* bq    = ca_in_b + i * 3 * D_;
        const float* bk    = bq + D_;
        const float* bv    = bq + 2 * D_;

        // --- self-attention over 1 token == two linear layers ---
        gemmNT(tbuf, wv_sa, bv_sa, buf2, B_, D_, D_, D_, D_, D_);
        gemmNT(buf2, sa_out_w + i * DD, sa_out_b + i * D_, buf3, B_, D_, D_, D_, D_, D_);
        add_ln_kernel<<<B_ / 8, 256>>>(tbuf, buf3, ln1_g + i * D_, ln1_b + i * D_);

        // --- cross-attention (factored: u = Wk_h^T q_h ; o_h = Wv_h c_h) ---
        gemmNT(tbuf, wq, bq, qb, B_, D_, D_, D_, D_, D_);
        gemmNN(qb, wk, nullptr, ub, B_, D_, HD_, D_, D_, H_ * D_,
               H_, HD_, HD_ * D_, D_, 0);
        attn_kernel<<<B_, 256, attn_smem>>>(qb, ub, kvb, bk, cb);
        gemmNT(cb, wv, bv, ob, B_, HD_, D_, H_ * D_, D_, D_,
               H_, D_, HD_ * D_, HD_, HD_);
        gemmNT(ob, ca_out_w + i * DD, ca_out_b + i * D_, buf3, B_, D_, D_, D_, D_, D_);
        add_ln_kernel<<<B_ / 8, 256>>>(tbuf, buf3, ln2_g + i * D_, ln2_b + i * D_);

        // --- feed-forward ---
        gemmNT(tbuf, lin1_w + (size_t)i * FF_ * D_, lin1_b + i * FF_, buf1,
               B_, FF_, D_, D_, D_, FF_, 1, 0, 0, 0, 0, true);
        gemmNT(buf1, lin2_w + (size_t)i * D_ * FF_, lin2_b + i * D_, buf3,
               B_, D_, FF_, FF_, FF_, D_);
        add_ln_kernel<<<B_ / 8, 256>>>(tbuf, buf3, ln3_g + i * D_, ln3_b + i * D_);
    }

    // 2) coarse branch + final combine
    gemmNT(x, region_w, region_b, coarse, B_, D_, D_, D_, D_, D_);
    final_kernel<<<B_ / 8, 256>>>(tbuf, coarse, out);
}